// round 1
// baseline (speedup 1.0000x reference)
#include <cuda_runtime.h>
#include <math.h>

#define D_EMBED 1024
#define SEQ     2048
#define BATCH   2
#define NHEAD   16
#define HDIM    64
#define NTOK    (BATCH * SEQ)      // 4096
#define LORA_R  8
#define LORA_SCALE_C 2.0f          // alpha/r = 16/8

// ---------------- scratch (no allocations allowed) ----------------
__device__ float g_qkv[(size_t)NTOK * 3 * D_EMBED];   // [B,S,3,H,hd] flattened
__device__ float g_attn[(size_t)NTOK * D_EMBED];      // attention out [B,S,D]
__device__ float g_xa[(size_t)NTOK * LORA_R];         // x @ A^T  (rank-8)

// ---------------- LoRA A projection: out[M,8] = X[M,K] @ Aw[8,K]^T ----------------
__global__ void lora_a_kernel(const float* __restrict__ X,
                              const float* __restrict__ Aw,
                              float* __restrict__ out) {
    __shared__ float As[LORA_R * D_EMBED];
    for (int i = threadIdx.x; i < LORA_R * D_EMBED; i += blockDim.x) As[i] = Aw[i];
    __syncthreads();
    int warp = threadIdx.x >> 5, lane = threadIdx.x & 31;
    int row = blockIdx.x * 8 + warp;
    const float* xr = X + (size_t)row * D_EMBED;
    float s[LORA_R];
#pragma unroll
    for (int r = 0; r < LORA_R; r++) s[r] = 0.f;
    for (int k = lane; k < D_EMBED; k += 32) {
        float xv = xr[k];
#pragma unroll
        for (int r = 0; r < LORA_R; r++) s[r] += xv * As[r * D_EMBED + k];
    }
#pragma unroll
    for (int off = 16; off > 0; off >>= 1) {
#pragma unroll
        for (int r = 0; r < LORA_R; r++) s[r] += __shfl_xor_sync(0xffffffffu, s[r], off);
    }
    if (lane == 0) {
#pragma unroll
        for (int r = 0; r < LORA_R; r++) out[(size_t)row * LORA_R + r] = s[r];
    }
}

// ---------------- SGEMM (NT): C[M,N] = A[M,K] @ W[N,K]^T + lora + bias ----------------
// 128x128 tile, BK=8, 256 threads, 8x8 microtile.
__global__ void sgemm_nt_lora(const float* __restrict__ A, const float* __restrict__ W,
                              const float* __restrict__ XA, const float* __restrict__ LB,
                              const float* __restrict__ bias, float* __restrict__ C,
                              int M, int N, int K, int hasBias) {
    __shared__ __align__(16) float As[8][128];
    __shared__ __align__(16) float Bs[8][128];
    int bm = blockIdx.y * 128, bn = blockIdx.x * 128;
    int tid = threadIdx.x;
    int tx = tid & 15, ty = tid >> 4;
    int lrow = tid >> 1, lc = (tid & 1) * 4;

    const float* Ap = A + (size_t)(bm + lrow) * K + lc;
    const float* Wp = W + (size_t)(bn + lrow) * K + lc;

    float acc[8][8];
#pragma unroll
    for (int i = 0; i < 8; i++)
#pragma unroll
        for (int j = 0; j < 8; j++) acc[i][j] = 0.f;

    for (int k0 = 0; k0 < K; k0 += 8) {
        float4 av = *(const float4*)(Ap + k0);
        float4 bv = *(const float4*)(Wp + k0);
        __syncthreads();
        As[lc + 0][lrow] = av.x; As[lc + 1][lrow] = av.y;
        As[lc + 2][lrow] = av.z; As[lc + 3][lrow] = av.w;
        Bs[lc + 0][lrow] = bv.x; Bs[lc + 1][lrow] = bv.y;
        Bs[lc + 2][lrow] = bv.z; Bs[lc + 3][lrow] = bv.w;
        __syncthreads();
#pragma unroll
        for (int kk = 0; kk < 8; kk++) {
            float ar[8], br[8];
            *(float4*)(ar)     = *(const float4*)&As[kk][ty * 8];
            *(float4*)(ar + 4) = *(const float4*)&As[kk][ty * 8 + 4];
            *(float4*)(br)     = *(const float4*)&Bs[kk][tx * 8];
            *(float4*)(br + 4) = *(const float4*)&Bs[kk][tx * 8 + 4];
#pragma unroll
            for (int i = 0; i < 8; i++)
#pragma unroll
                for (int j = 0; j < 8; j++) acc[i][j] += ar[i] * br[j];
        }
    }

    // LoRA rank-8 correction: acc += (XA[row,:] . LB[col,:]) * scale
#pragma unroll
    for (int r = 0; r < LORA_R; r++) {
        float xa[8], lb[8];
#pragma unroll
        for (int i = 0; i < 8; i++)
            xa[i] = XA[(size_t)(bm + ty * 8 + i) * LORA_R + r] * LORA_SCALE_C;
#pragma unroll
        for (int j = 0; j < 8; j++)
            lb[j] = LB[(size_t)(bn + tx * 8 + j) * LORA_R + r];
#pragma unroll
        for (int i = 0; i < 8; i++)
#pragma unroll
            for (int j = 0; j < 8; j++) acc[i][j] += xa[i] * lb[j];
    }
    if (hasBias) {
        float bb[8];
#pragma unroll
        for (int j = 0; j < 8; j++) bb[j] = bias[bn + tx * 8 + j];
#pragma unroll
        for (int i = 0; i < 8; i++)
#pragma unroll
            for (int j = 0; j < 8; j++) acc[i][j] += bb[j];
    }
#pragma unroll
    for (int i = 0; i < 8; i++) {
        float* cp = C + (size_t)(bm + ty * 8 + i) * N + bn + tx * 8;
        *(float4*)(cp)     = make_float4(acc[i][0], acc[i][1], acc[i][2], acc[i][3]);
        *(float4*)(cp + 4) = make_float4(acc[i][4], acc[i][5], acc[i][6], acc[i][7]);
    }
}

// ---------------- RoPE in-place on q,k in g_qkv [B,S,3,H,hd] ----------------
__global__ void rope_kernel(float* __restrict__ qkv) {
    int t = blockIdx.x * blockDim.x + threadIdx.x;   // 2*2048*16*32 threads
    int i = t & 31;
    int h = (t >> 5) & 15;
    int s = (t >> 9) & 2047;
    int b = t >> 20;
    float inv_freq = expf(-(float)i * (logf(10000.f) / 32.f));  // 10000^{-i/32}
    float ang = (float)s * inv_freq;
    float sn, cs;
    sincosf(ang, &sn, &cs);
    size_t base = ((size_t)(b * SEQ + s) * 3) * D_EMBED + h * HDIM + i;
    float q0 = qkv[base], q1 = qkv[base + 32];
    qkv[base]      = q0 * cs - q1 * sn;
    qkv[base + 32] = q1 * cs + q0 * sn;
    size_t kb = base + D_EMBED;
    float k0 = qkv[kb], k1 = qkv[kb + 32];
    qkv[kb]      = k0 * cs - k1 * sn;
    qkv[kb + 32] = k1 * cs + k0 * sn;
}

// ---------------- Causal flash attention, fp32, 64x64 tiles ----------------
// grid: (S/64, B*H); block 256 threads (16x16, 4x4 microtiles).
__global__ void flash_attn_kernel(const float* __restrict__ qkv, float* __restrict__ out) {
    extern __shared__ __align__(16) float sm[];
    float* Qt   = sm;                 // [64][65]  (d-major, padded)
    float* Kt   = Qt + 64 * 65;       // [64][65]
    float* Vs   = Kt + 64 * 65;       // [64][64]  (c-major)
    float* Ps   = Vs + 64 * 64;       // [64][64]  (r-major)
    float* mrow = Ps + 64 * 64;       // [64]
    float* lrow = mrow + 64;          // [64]

    int qb = blockIdx.x;              // query tile
    int bh = blockIdx.y;
    int b = bh >> 4, h = bh & 15;
    int q0 = qb * 64;
    int tid = threadIdx.x;
    int tx = tid & 15, ty = tid >> 4;

    // load Q tile transposed
    {
        int r = tid >> 2, dq = (tid & 3) * 16;
        const float* qp = qkv + ((size_t)(b * SEQ + q0 + r) * 3) * D_EMBED + h * HDIM;
#pragma unroll
        for (int j = 0; j < 16; j += 4) {
            float4 v = *(const float4*)(qp + dq + j);
            Qt[(dq + j + 0) * 65 + r] = v.x;
            Qt[(dq + j + 1) * 65 + r] = v.y;
            Qt[(dq + j + 2) * 65 + r] = v.z;
            Qt[(dq + j + 3) * 65 + r] = v.w;
        }
    }
    if (tid < 64) { mrow[tid] = -1e30f; lrow[tid] = 0.f; }

    float o[4][4];
#pragma unroll
    for (int i = 0; i < 4; i++)
#pragma unroll
        for (int j = 0; j < 4; j++) o[i][j] = 0.f;

    int ntiles = qb + 1;
    for (int jt = 0; jt < ntiles; jt++) {
        __syncthreads();   // protect Kt/Vs/Ps from previous iteration readers
        int k0 = jt * 64;
        {
            int c = tid >> 2, dq = (tid & 3) * 16;
            const float* kp = qkv + ((size_t)(b * SEQ + k0 + c) * 3 + 1) * D_EMBED + h * HDIM;
            const float* vp = qkv + ((size_t)(b * SEQ + k0 + c) * 3 + 2) * D_EMBED + h * HDIM;
#pragma unroll
            for (int j = 0; j < 16; j += 4) {
                float4 kv = *(const float4*)(kp + dq + j);
                Kt[(dq + j + 0) * 65 + c] = kv.x;
                Kt[(dq + j + 1) * 65 + c] = kv.y;
                Kt[(dq + j + 2) * 65 + c] = kv.z;
                Kt[(dq + j + 3) * 65 + c] = kv.w;
                *(float4*)&Vs[c * 64 + dq + j] = *(const float4*)(vp + dq + j);
            }
        }
        __syncthreads();

        // scores = Q K^T
        float acc[4][4];
#pragma unroll
        for (int i = 0; i < 4; i++)
#pragma unroll
            for (int j = 0; j < 4; j++) acc[i][j] = 0.f;
#pragma unroll 4
        for (int d = 0; d < 64; d++) {
            float ar[4], br[4];
#pragma unroll
            for (int i = 0; i < 4; i++) ar[i] = Qt[d * 65 + ty * 4 + i];
#pragma unroll
            for (int j = 0; j < 4; j++) br[j] = Kt[d * 65 + tx * 4 + j];
#pragma unroll
            for (int i = 0; i < 4; i++)
#pragma unroll
                for (int j = 0; j < 4; j++) acc[i][j] += ar[i] * br[j];
        }

        const float sc = 0.125f;   // hd^-0.5
        bool diag = (jt == qb);
#pragma unroll
        for (int i = 0; i < 4; i++)
#pragma unroll
            for (int j = 0; j < 4; j++) {
                float v = acc[i][j] * sc;
                if (diag && (tx * 4 + j > ty * 4 + i)) v = -1e30f;
                acc[i][j] = v;
            }

        // partial row max + reduce across the 16 tx lanes (same half-warp)
        float pm[4];
#pragma unroll
        for (int i = 0; i < 4; i++)
            pm[i] = fmaxf(fmaxf(acc[i][0], acc[i][1]), fmaxf(acc[i][2], acc[i][3]));
#pragma unroll
        for (int off = 8; off > 0; off >>= 1)
#pragma unroll
            for (int i = 0; i < 4; i++)
                pm[i] = fmaxf(pm[i], __shfl_xor_sync(0xffffffffu, pm[i], off));

        float mnew[4], al[4];
#pragma unroll
        for (int i = 0; i < 4; i++) {
            float mo = mrow[ty * 4 + i];
            mnew[i] = fmaxf(mo, pm[i]);
            al[i] = __expf(mo - mnew[i]);
        }
        float psum[4];
#pragma unroll
        for (int i = 0; i < 4; i++) {
            psum[i] = 0.f;
#pragma unroll
            for (int j = 0; j < 4; j++) {
                float p = __expf(acc[i][j] - mnew[i]);
                acc[i][j] = p;
                psum[i] += p;
            }
        }
#pragma unroll
        for (int off = 8; off > 0; off >>= 1)
#pragma unroll
            for (int i = 0; i < 4; i++)
                psum[i] += __shfl_xor_sync(0xffffffffu, psum[i], off);

        __syncwarp();
        if (tx == 0) {
#pragma unroll
            for (int i = 0; i < 4; i++) {
                mrow[ty * 4 + i] = mnew[i];
                lrow[ty * 4 + i] = lrow[ty * 4 + i] * al[i] + psum[i];
            }
        }

        // rescale running output, stage P
#pragma unroll
        for (int i = 0; i < 4; i++) {
#pragma unroll
            for (int j = 0; j < 4; j++) o[i][j] *= al[i];
            *(float4*)&Ps[(ty * 4 + i) * 64 + tx * 4] =
                make_float4(acc[i][0], acc[i][1], acc[i][2], acc[i][3]);
        }
        __syncthreads();

        // O += P @ V
#pragma unroll 4
        for (int c = 0; c < 64; c++) {
            float pr[4];
#pragma unroll
            for (int i = 0; i < 4; i++) pr[i] = Ps[(ty * 4 + i) * 64 + c];
            float4 vv = *(const float4*)&Vs[c * 64 + tx * 4];
#pragma unroll
            for (int i = 0; i < 4; i++) {
                o[i][0] += pr[i] * vv.x;
                o[i][1] += pr[i] * vv.y;
                o[i][2] += pr[i] * vv.z;
                o[i][3] += pr[i] * vv.w;
            }
        }
    }

    // epilogue: normalize and write [B,S,H*hd]
#pragma unroll
    for (int i = 0; i < 4; i++) {
        float inv = 1.f / lrow[ty * 4 + i];
        float* op = out + (size_t)(b * SEQ + q0 + ty * 4 + i) * D_EMBED + h * HDIM + tx * 4;
        *(float4*)op = make_float4(o[i][0] * inv, o[i][1] * inv, o[i][2] * inv, o[i][3] * inv);
    }
}

// ---------------- launcher ----------------
extern "C" void kernel_launch(void* const* d_in, const int* in_sizes, int n_in,
                              void* d_out, int out_size) {
    const float* x     = (const float*)d_in[0];
    const float* Wqkv  = (const float*)d_in[1];
    const float* Aqkv  = (const float*)d_in[2];
    const float* Bqkv  = (const float*)d_in[3];
    const float* Wproj = (const float*)d_in[4];
    const float* bproj = (const float*)d_in[5];
    const float* Aproj = (const float*)d_in[6];
    const float* Bproj = (const float*)d_in[7];

    float *qkv, *attn, *xa;
    cudaGetSymbolAddress((void**)&qkv,  g_qkv);
    cudaGetSymbolAddress((void**)&attn, g_attn);
    cudaGetSymbolAddress((void**)&xa,   g_xa);

    // 1) LoRA-A for qkv
    lora_a_kernel<<<NTOK / 8, 256>>>(x, Aqkv, xa);
    // 2) QKV GEMM + LoRA-B
    sgemm_nt_lora<<<dim3(3 * D_EMBED / 128, NTOK / 128), 256>>>(
        x, Wqkv, xa, Bqkv, nullptr, qkv, NTOK, 3 * D_EMBED, D_EMBED, 0);
    // 3) RoPE on q,k
    rope_kernel<<<(BATCH * SEQ * NHEAD * 32) / 256, 256>>>(qkv);
    // 4) causal flash attention
    int smem = (64 * 65 * 2 + 64 * 64 * 2 + 128) * (int)sizeof(float);
    cudaFuncSetAttribute(flash_attn_kernel,
                         cudaFuncAttributeMaxDynamicSharedMemorySize, smem);
    flash_attn_kernel<<<dim3(SEQ / 64, BATCH * NHEAD), 256, smem>>>(qkv, attn);
    // 5) LoRA-A for proj
    lora_a_kernel<<<NTOK / 8, 256>>>(attn, Aproj, xa);
    // 6) output projection + bias + LoRA-B  -> d_out
    sgemm_nt_lora<<<dim3(D_EMBED / 128, NTOK / 128), 256>>>(
        attn, Wproj, xa, Bproj, bproj, (float*)d_out, NTOK, D_EMBED, D_EMBED, 1);
}

// round 3
// speedup vs baseline: 2.1493x; 2.1493x over previous
#include <cuda_runtime.h>
#include <math.h>
#include <stdint.h>

#define D_EMBED 1024
#define SEQ     2048
#define BATCH   2
#define NHEAD   16
#define HDIM    64
#define NTOK    (BATCH * SEQ)      // 4096
#define LORA_R  8
#define LORA_SCALE_C 2.0f          // alpha/r = 16/8

// ---------------- scratch (no allocations allowed) ----------------
__device__ float g_qkv[(size_t)NTOK * 3 * D_EMBED];   // [B,S,3,H,hd]
__device__ float g_attn[(size_t)NTOK * D_EMBED];      // attention out [B,S,D]
__device__ float g_xa[(size_t)NTOK * LORA_R];         // x @ A^T

// ---------------- helpers ----------------
__device__ __forceinline__ uint32_t f2tf(float x) {
    uint32_t u; asm("cvt.rna.tf32.f32 %0, %1;" : "=r"(u) : "f"(x)); return u;
}
__device__ __forceinline__ void mma_tf32(float c[4],
                                         uint32_t a0, uint32_t a1, uint32_t a2, uint32_t a3,
                                         uint32_t b0, uint32_t b1) {
    asm volatile(
        "mma.sync.aligned.m16n8k8.row.col.f32.tf32.tf32.f32 "
        "{%0,%1,%2,%3}, {%4,%5,%6,%7}, {%8,%9}, {%0,%1,%2,%3};"
        : "+f"(c[0]), "+f"(c[1]), "+f"(c[2]), "+f"(c[3])
        : "r"(a0), "r"(a1), "r"(a2), "r"(a3), "r"(b0), "r"(b1));
}

// ---------------- LoRA A projection: out[M,8] = X[M,K] @ Aw[8,K]^T ----------------
__global__ void lora_a_kernel(const float* __restrict__ X,
                              const float* __restrict__ Aw,
                              float* __restrict__ out) {
    __shared__ float As[LORA_R * D_EMBED];
    for (int i = threadIdx.x; i < LORA_R * D_EMBED; i += blockDim.x) As[i] = Aw[i];
    __syncthreads();
    int warp = threadIdx.x >> 5, lane = threadIdx.x & 31;
    int row = blockIdx.x * 8 + warp;
    const float* xr = X + (size_t)row * D_EMBED;
    float s[LORA_R];
#pragma unroll
    for (int r = 0; r < LORA_R; r++) s[r] = 0.f;
    for (int k = lane; k < D_EMBED; k += 32) {
        float xv = xr[k];
#pragma unroll
        for (int r = 0; r < LORA_R; r++) s[r] += xv * As[r * D_EMBED + k];
    }
#pragma unroll
    for (int off = 16; off > 0; off >>= 1) {
#pragma unroll
        for (int r = 0; r < LORA_R; r++) s[r] += __shfl_xor_sync(0xffffffffu, s[r], off);
    }
    if (lane == 0) {
#pragma unroll
        for (int r = 0; r < LORA_R; r++) out[(size_t)row * LORA_R + r] = s[r];
    }
}

// ---------------- TF32 GEMM (NT): C = A[M,K] @ W[N,K]^T + LoRA + bias ----------------
// 128x128 tile, BK=32, 256 threads = 8 warps (4m x 2n), warp tile 32x64.
__global__ __launch_bounds__(256) void gemm_tf32_lora(
    const float* __restrict__ A, const float* __restrict__ W,
    const float* __restrict__ XA, const float* __restrict__ LB,
    const float* __restrict__ bias, float* __restrict__ C,
    int M, int N, int K, int hasBias) {
    __shared__ float As[32][136];   // [k][m], pad 8 -> conflict-free frag loads
    __shared__ float Bs[32][136];   // [k][n]
    int bm = blockIdx.y * 128, bn = blockIdx.x * 128;
    int tid = threadIdx.x;
    int warp = tid >> 5, lane = tid & 31;
    int wm = warp >> 1, wn = warp & 1;
    int qid = lane >> 2, qt = lane & 3;

    int lr = tid >> 1;            // 0..127 (row of tile)
    int lk = (tid & 1) * 16;      // 0 or 16

    const float* Ap = A + (size_t)(bm + lr) * K + lk;
    const float* Wp = W + (size_t)(bn + lr) * K + lk;

    float acc[2][8][4];
#pragma unroll
    for (int mi = 0; mi < 2; mi++)
#pragma unroll
        for (int f = 0; f < 8; f++)
#pragma unroll
            for (int c = 0; c < 4; c++) acc[mi][f][c] = 0.f;

    for (int k0 = 0; k0 < K; k0 += 32) {
        float4 av[4], bv[4];
#pragma unroll
        for (int i = 0; i < 4; i++) {
            av[i] = *(const float4*)(Ap + k0 + i * 4);
            bv[i] = *(const float4*)(Wp + k0 + i * 4);
        }
        __syncthreads();
#pragma unroll
        for (int i = 0; i < 4; i++) {
            const float* a4 = (const float*)&av[i];
            const float* b4 = (const float*)&bv[i];
#pragma unroll
            for (int j = 0; j < 4; j++) {
                As[lk + i * 4 + j][lr] = __uint_as_float(f2tf(a4[j]));
                Bs[lk + i * 4 + j][lr] = __uint_as_float(f2tf(b4[j]));
            }
        }
        __syncthreads();

#pragma unroll
        for (int kk = 0; kk < 32; kk += 8) {
            uint32_t a[2][4];
#pragma unroll
            for (int mi = 0; mi < 2; mi++) {
                int m = wm * 32 + mi * 16 + qid;
                a[mi][0] = __float_as_uint(As[kk + qt][m]);
                a[mi][1] = __float_as_uint(As[kk + qt][m + 8]);
                a[mi][2] = __float_as_uint(As[kk + qt + 4][m]);
                a[mi][3] = __float_as_uint(As[kk + qt + 4][m + 8]);
            }
#pragma unroll
            for (int f = 0; f < 8; f++) {
                int n = wn * 64 + f * 8 + qid;
                uint32_t b0 = __float_as_uint(Bs[kk + qt][n]);
                uint32_t b1 = __float_as_uint(Bs[kk + qt + 4][n]);
                mma_tf32(acc[0][f], a[0][0], a[0][1], a[0][2], a[0][3], b0, b1);
                mma_tf32(acc[1][f], a[1][0], a[1][1], a[1][2], a[1][3], b0, b1);
            }
        }
    }

    // LoRA rank-8: acc += scale * XA[row,:] . LB[col,:]
    int r0[2], r1[2];
#pragma unroll
    for (int mi = 0; mi < 2; mi++) {
        r0[mi] = bm + wm * 32 + mi * 16 + qid;
        r1[mi] = r0[mi] + 8;
    }
#pragma unroll
    for (int rr = 0; rr < LORA_R; rr++) {
        float xa0[2], xa1[2];
#pragma unroll
        for (int mi = 0; mi < 2; mi++) {
            xa0[mi] = XA[(size_t)r0[mi] * LORA_R + rr] * LORA_SCALE_C;
            xa1[mi] = XA[(size_t)r1[mi] * LORA_R + rr] * LORA_SCALE_C;
        }
#pragma unroll
        for (int f = 0; f < 8; f++) {
            int c0 = bn + wn * 64 + f * 8 + 2 * qt;
            float lb0 = LB[(size_t)c0 * LORA_R + rr];
            float lb1 = LB[(size_t)(c0 + 1) * LORA_R + rr];
#pragma unroll
            for (int mi = 0; mi < 2; mi++) {
                acc[mi][f][0] += xa0[mi] * lb0;
                acc[mi][f][1] += xa0[mi] * lb1;
                acc[mi][f][2] += xa1[mi] * lb0;
                acc[mi][f][3] += xa1[mi] * lb1;
            }
        }
    }
    if (hasBias) {
#pragma unroll
        for (int f = 0; f < 8; f++) {
            int c0 = bn + wn * 64 + f * 8 + 2 * qt;
            float b0 = bias[c0], b1 = bias[c0 + 1];
#pragma unroll
            for (int mi = 0; mi < 2; mi++) {
                acc[mi][f][0] += b0; acc[mi][f][1] += b1;
                acc[mi][f][2] += b0; acc[mi][f][3] += b1;
            }
        }
    }
#pragma unroll
    for (int mi = 0; mi < 2; mi++)
#pragma unroll
        for (int f = 0; f < 8; f++) {
            int c0 = bn + wn * 64 + f * 8 + 2 * qt;
            *(float2*)(C + (size_t)r0[mi] * N + c0) = make_float2(acc[mi][f][0], acc[mi][f][1]);
            *(float2*)(C + (size_t)r1[mi] * N + c0) = make_float2(acc[mi][f][2], acc[mi][f][3]);
        }
}

// ---------------- RoPE in-place on q,k in g_qkv [B,S,3,H,hd] ----------------
__global__ void rope_kernel(float* __restrict__ qkv) {
    int t = blockIdx.x * blockDim.x + threadIdx.x;
    int i = t & 31;
    int h = (t >> 5) & 15;
    int s = (t >> 9) & 2047;
    int b = t >> 20;
    float inv_freq = expf(-(float)i * (logf(10000.f) / 32.f));
    float ang = (float)s * inv_freq;
    float sn, cs;
    sincosf(ang, &sn, &cs);
    size_t base = ((size_t)(b * SEQ + s) * 3) * D_EMBED + h * HDIM + i;
    float q0 = qkv[base], q1 = qkv[base + 32];
    qkv[base]      = q0 * cs - q1 * sn;
    qkv[base + 32] = q1 * cs + q0 * sn;
    size_t kb = base + D_EMBED;
    float k0 = qkv[kb], k1 = qkv[kb + 32];
    qkv[kb]      = k0 * cs - k1 * sn;
    qkv[kb + 32] = k1 * cs + k0 * sn;
}

// ---------------- TF32 causal flash attention ----------------
// Br=64, Bc=64, hd=64; 128 threads = 4 warps, 16 q-rows per warp (warp-private softmax).
__global__ __launch_bounds__(128) void flash_tf32(const float* __restrict__ qkv,
                                                  float* __restrict__ out) {
    extern __shared__ float sm[];
    float* Kt = sm;               // [64 d][72]   Kt[d*72 + key] (tf32 bits)
    float* Vs = Kt + 64 * 72;     // [64 key][72] Vs[key*72 + d] (tf32 bits)
    float* Ps = Vs + 64 * 72;     // per-warp [16][68] P staging (tf32 bits)

    int qb = blockIdx.x, bh = blockIdx.y;
    int b = bh >> 4, h = bh & 15;
    int q0 = qb * 64;
    int tid = threadIdx.x, warp = tid >> 5, lane = tid & 31;
    int qid = lane >> 2, qt = lane & 3;
    float* Pw = Ps + warp * 16 * 68;

    int r = tid >> 1, half = tid & 1;

    // ---- stage Q (row-major, raw fp32) in Vs, then extract A frags (scaled, tf32)
    {
        const float* qp = qkv + ((size_t)(b * SEQ + q0 + r) * 3) * D_EMBED + h * HDIM + half * 32;
        float* dst = Vs + r * 72 + half * 32;
#pragma unroll
        for (int i = 0; i < 8; i++)
            *(float4*)(dst + i * 4) = *(const float4*)(qp + i * 4);
    }
    __syncthreads();
    uint32_t qa[8][4];
    {
        int m0 = warp * 16 + qid, m1 = m0 + 8;
        const float sc = 0.125f;  // fold hd^-0.5 into Q
#pragma unroll
        for (int kk = 0; kk < 8; kk++) {
            qa[kk][0] = f2tf(sc * Vs[m0 * 72 + kk * 8 + qt]);
            qa[kk][1] = f2tf(sc * Vs[m1 * 72 + kk * 8 + qt]);
            qa[kk][2] = f2tf(sc * Vs[m0 * 72 + kk * 8 + qt + 4]);
            qa[kk][3] = f2tf(sc * Vs[m1 * 72 + kk * 8 + qt + 4]);
        }
    }

    float m0 = -1e30f, m1 = -1e30f, l0 = 0.f, l1 = 0.f;
    float o[8][4];
#pragma unroll
    for (int f = 0; f < 8; f++)
#pragma unroll
        for (int c = 0; c < 4; c++) o[f][c] = 0.f;

    int ntiles = qb + 1;
    for (int jt = 0; jt < ntiles; jt++) {
        __syncthreads();   // protect Vs (Q staging / prev tile) and Kt readers
        {
            const float* kp = qkv + ((size_t)(b * SEQ + jt * 64 + r) * 3 + 1) * D_EMBED + h * HDIM + half * 32;
            const float* vp = qkv + ((size_t)(b * SEQ + jt * 64 + r) * 3 + 2) * D_EMBED + h * HDIM + half * 32;
#pragma unroll
            for (int i = 0; i < 8; i++) {
                int d = half * 32 + i * 4;
                float4 kv = *(const float4*)(kp + i * 4);
                Kt[(d + 0) * 72 + r] = __uint_as_float(f2tf(kv.x));
                Kt[(d + 1) * 72 + r] = __uint_as_float(f2tf(kv.y));
                Kt[(d + 2) * 72 + r] = __uint_as_float(f2tf(kv.z));
                Kt[(d + 3) * 72 + r] = __uint_as_float(f2tf(kv.w));
                float4 vv = *(const float4*)(vp + i * 4);
                float4 vc;
                vc.x = __uint_as_float(f2tf(vv.x));
                vc.y = __uint_as_float(f2tf(vv.y));
                vc.z = __uint_as_float(f2tf(vv.z));
                vc.w = __uint_as_float(f2tf(vv.w));
                *(float4*)(Vs + r * 72 + d) = vc;
            }
        }
        __syncthreads();

        // ---- S = Q K^T (per warp: 16 x 64)
        float s[8][4];
#pragma unroll
        for (int f = 0; f < 8; f++)
#pragma unroll
            for (int c = 0; c < 4; c++) s[f][c] = 0.f;
#pragma unroll
        for (int kk = 0; kk < 8; kk++) {
#pragma unroll
            for (int f = 0; f < 8; f++) {
                uint32_t b0 = __float_as_uint(Kt[(kk * 8 + qt) * 72 + f * 8 + qid]);
                uint32_t b1 = __float_as_uint(Kt[(kk * 8 + qt + 4) * 72 + f * 8 + qid]);
                mma_tf32(s[f], qa[kk][0], qa[kk][1], qa[kk][2], qa[kk][3], b0, b1);
            }
        }

        // ---- causal mask on diagonal tile
        if (jt == qb) {
            int lr0 = warp * 16 + qid, lr1 = lr0 + 8;
#pragma unroll
            for (int f = 0; f < 8; f++) {
                int lc = f * 8 + 2 * qt;
                if (lc > lr0)     s[f][0] = -1e30f;
                if (lc + 1 > lr0) s[f][1] = -1e30f;
                if (lc > lr1)     s[f][2] = -1e30f;
                if (lc + 1 > lr1) s[f][3] = -1e30f;
            }
        }

        // ---- online softmax (rows are quad-shared)
        float rm0 = -1e30f, rm1 = -1e30f;
#pragma unroll
        for (int f = 0; f < 8; f++) {
            rm0 = fmaxf(rm0, fmaxf(s[f][0], s[f][1]));
            rm1 = fmaxf(rm1, fmaxf(s[f][2], s[f][3]));
        }
        rm0 = fmaxf(rm0, __shfl_xor_sync(0xffffffffu, rm0, 1));
        rm0 = fmaxf(rm0, __shfl_xor_sync(0xffffffffu, rm0, 2));
        rm1 = fmaxf(rm1, __shfl_xor_sync(0xffffffffu, rm1, 1));
        rm1 = fmaxf(rm1, __shfl_xor_sync(0xffffffffu, rm1, 2));

        float mn0 = fmaxf(m0, rm0), mn1 = fmaxf(m1, rm1);
        float al0 = __expf(m0 - mn0), al1 = __expf(m1 - mn1);
        float rs0 = 0.f, rs1 = 0.f;
#pragma unroll
        for (int f = 0; f < 8; f++) {
            s[f][0] = __expf(s[f][0] - mn0);
            s[f][1] = __expf(s[f][1] - mn0);
            s[f][2] = __expf(s[f][2] - mn1);
            s[f][3] = __expf(s[f][3] - mn1);
            rs0 += s[f][0] + s[f][1];
            rs1 += s[f][2] + s[f][3];
        }
        rs0 += __shfl_xor_sync(0xffffffffu, rs0, 1);
        rs0 += __shfl_xor_sync(0xffffffffu, rs0, 2);
        rs1 += __shfl_xor_sync(0xffffffffu, rs1, 1);
        rs1 += __shfl_xor_sync(0xffffffffu, rs1, 2);
        l0 = l0 * al0 + rs0;
        l1 = l1 * al1 + rs1;
        m0 = mn0; m1 = mn1;
#pragma unroll
        for (int f = 0; f < 8; f++) {
            o[f][0] *= al0; o[f][1] *= al0;
            o[f][2] *= al1; o[f][3] *= al1;
        }

        // ---- stage P (tf32) in per-warp smem, then PV mma into O
        __syncwarp();
#pragma unroll
        for (int f = 0; f < 8; f++) {
            float2 p0 = make_float2(__uint_as_float(f2tf(s[f][0])), __uint_as_float(f2tf(s[f][1])));
            float2 p1 = make_float2(__uint_as_float(f2tf(s[f][2])), __uint_as_float(f2tf(s[f][3])));
            *(float2*)(Pw + qid * 68 + f * 8 + 2 * qt) = p0;
            *(float2*)(Pw + (qid + 8) * 68 + f * 8 + 2 * qt) = p1;
        }
        __syncwarp();
#pragma unroll
        for (int kk = 0; kk < 8; kk++) {
            uint32_t pa0 = __float_as_uint(Pw[qid * 68 + kk * 8 + qt]);
            uint32_t pa1 = __float_as_uint(Pw[(qid + 8) * 68 + kk * 8 + qt]);
            uint32_t pa2 = __float_as_uint(Pw[qid * 68 + kk * 8 + qt + 4]);
            uint32_t pa3 = __float_as_uint(Pw[(qid + 8) * 68 + kk * 8 + qt + 4]);
#pragma unroll
            for (int f = 0; f < 8; f++) {
                uint32_t b0 = __float_as_uint(Vs[(kk * 8 + qt) * 72 + f * 8 + qid]);
                uint32_t b1 = __float_as_uint(Vs[(kk * 8 + qt + 4) * 72 + f * 8 + qid]);
                mma_tf32(o[f], pa0, pa1, pa2, pa3, b0, b1);
            }
        }
    }

    // ---- epilogue: normalize, write [B,S,H*hd]
    float inv0 = 1.f / l0, inv1 = 1.f / l1;
    size_t ro = (size_t)(b * SEQ + q0 + warp * 16 + qid) * D_EMBED + h * HDIM;
#pragma unroll
    for (int f = 0; f < 8; f++) {
        *(float2*)(out + ro + f * 8 + 2 * qt) =
            make_float2(o[f][0] * inv0, o[f][1] * inv0);
        *(float2*)(out + ro + 8 * D_EMBED + f * 8 + 2 * qt) =
            make_float2(o[f][2] * inv1, o[f][3] * inv1);
    }
}

// ---------------- launcher ----------------
extern "C" void kernel_launch(void* const* d_in, const int* in_sizes, int n_in,
                              void* d_out, int out_size) {
    const float* x     = (const float*)d_in[0];
    const float* Wqkv  = (const float*)d_in[1];
    const float* Aqkv  = (const float*)d_in[2];
    const float* Bqkv  = (const float*)d_in[3];
    const float* Wproj = (const float*)d_in[4];
    const float* bproj = (const float*)d_in[5];
    const float* Aproj = (const float*)d_in[6];
    const float* Bproj = (const float*)d_in[7];

    float *qkv, *attn, *xa;
    cudaGetSymbolAddress((void**)&qkv,  g_qkv);
    cudaGetSymbolAddress((void**)&attn, g_attn);
    cudaGetSymbolAddress((void**)&xa,   g_xa);

    // 1) LoRA-A for qkv
    lora_a_kernel<<<NTOK / 8, 256>>>(x, Aqkv, xa);
    // 2) QKV GEMM + LoRA-B (tf32 tensor cores)
    gemm_tf32_lora<<<dim3(3 * D_EMBED / 128, NTOK / 128), 256>>>(
        x, Wqkv, xa, Bqkv, nullptr, qkv, NTOK, 3 * D_EMBED, D_EMBED, 0);
    // 3) RoPE on q,k
    rope_kernel<<<(BATCH * SEQ * NHEAD * 32) / 256, 256>>>(qkv);
    // 4) causal flash attention (tf32 tensor cores)
    int smem = (64 * 72 * 2 + 4 * 16 * 68) * (int)sizeof(float);
    cudaFuncSetAttribute(flash_tf32,
                         cudaFuncAttributeMaxDynamicSharedMemorySize, smem);
    flash_tf32<<<dim3(SEQ / 64, BATCH * NHEAD), 128, smem>>>(qkv, attn);
    // 5) LoRA-A for proj
    lora_a_kernel<<<NTOK / 8, 256>>>(attn, Aproj, xa);
    // 6) output projection + bias + LoRA-B -> d_out
    gemm_tf32_lora<<<dim3(D_EMBED / 128, NTOK / 128), 256>>>(
        attn, Wproj, xa, Bproj, bproj, (float*)d_out, NTOK, D_EMBED, D_EMBED, 1);
}

// round 4
// speedup vs baseline: 2.6003x; 1.2098x over previous
#include <cuda_runtime.h>
#include <math.h>
#include <stdint.h>

#define D_EMBED 1024
#define SEQ     2048
#define BATCH   2
#define NHEAD   16
#define HDIM    64
#define NTOK    (BATCH * SEQ)      // 4096
#define LORA_R  8
#define LORA_SCALE_C 2.0f          // alpha/r = 16/8

// ---------------- scratch (no allocations allowed) ----------------
__device__ float g_qkv[(size_t)NTOK * 3 * D_EMBED];   // [B,S,3,H,hd]
__device__ float g_attn[(size_t)NTOK * D_EMBED];      // attention out [B,S,D]
__device__ float g_xa[(size_t)NTOK * LORA_R];         // x @ A^T

// ---------------- helpers ----------------
__device__ __forceinline__ uint32_t f2tf(float x) {
    uint32_t u; asm("cvt.rna.tf32.f32 %0, %1;" : "=r"(u) : "f"(x)); return u;
}
__device__ __forceinline__ void mma_tf32(float c[4],
                                         uint32_t a0, uint32_t a1, uint32_t a2, uint32_t a3,
                                         uint32_t b0, uint32_t b1) {
    asm volatile(
        "mma.sync.aligned.m16n8k8.row.col.f32.tf32.tf32.f32 "
        "{%0,%1,%2,%3}, {%4,%5,%6,%7}, {%8,%9}, {%0,%1,%2,%3};"
        : "+f"(c[0]), "+f"(c[1]), "+f"(c[2]), "+f"(c[3])
        : "r"(a0), "r"(a1), "r"(a2), "r"(a3), "r"(b0), "r"(b1));
}

// ---------------- LoRA A projection: out[M,8] = X[M,K] @ Aw[8,K]^T ----------------
__global__ void lora_a_kernel(const float* __restrict__ X,
                              const float* __restrict__ Aw,
                              float* __restrict__ out) {
    __shared__ float As[LORA_R * D_EMBED];
    for (int i = threadIdx.x; i < LORA_R * D_EMBED; i += blockDim.x) As[i] = Aw[i];
    __syncthreads();
    int warp = threadIdx.x >> 5, lane = threadIdx.x & 31;
    int row = blockIdx.x * 8 + warp;
    const float* xr = X + (size_t)row * D_EMBED;
    float s[LORA_R];
#pragma unroll
    for (int r = 0; r < LORA_R; r++) s[r] = 0.f;
    for (int k = lane; k < D_EMBED; k += 32) {
        float xv = xr[k];
#pragma unroll
        for (int r = 0; r < LORA_R; r++) s[r] += xv * As[r * D_EMBED + k];
    }
#pragma unroll
    for (int off = 16; off > 0; off >>= 1) {
#pragma unroll
        for (int r = 0; r < LORA_R; r++) s[r] += __shfl_xor_sync(0xffffffffu, s[r], off);
    }
    if (lane == 0) {
#pragma unroll
        for (int r = 0; r < LORA_R; r++) out[(size_t)row * LORA_R + r] = s[r];
    }
}

// ---------------- TF32 GEMM (NT): C = A[M,K] @ W[N,K]^T + LoRA + bias ----------------
// 128x128 tile, BK=32, 256 threads = 8 warps (4m x 2n), warp tile 32x64.
// Software-pipelined: next K-chunk's LDGs issued before the MMA section.
__global__ __launch_bounds__(256) void gemm_tf32_lora(
    const float* __restrict__ A, const float* __restrict__ W,
    const float* __restrict__ XA, const float* __restrict__ LB,
    const float* __restrict__ bias, float* __restrict__ C,
    int M, int N, int K, int hasBias) {
    __shared__ float As[32][136];   // [k][m], pad 8 -> conflict-free frag loads
    __shared__ float Bs[32][136];   // [k][n]
    int bm = blockIdx.y * 128, bn = blockIdx.x * 128;
    int tid = threadIdx.x;
    int warp = tid >> 5, lane = tid & 31;
    int wm = warp >> 1, wn = warp & 1;
    int qid = lane >> 2, qt = lane & 3;

    int lr = tid >> 1;            // 0..127 (row of tile)
    int lk = (tid & 1) * 16;      // 0 or 16

    const float* Ap = A + (size_t)(bm + lr) * K + lk;
    const float* Wp = W + (size_t)(bn + lr) * K + lk;

    float acc[2][8][4];
#pragma unroll
    for (int mi = 0; mi < 2; mi++)
#pragma unroll
        for (int f = 0; f < 8; f++)
#pragma unroll
            for (int c = 0; c < 4; c++) acc[mi][f][c] = 0.f;

    float4 av[4], bv[4];
#pragma unroll
    for (int i = 0; i < 4; i++) {              // prefetch k0 = 0
        av[i] = *(const float4*)(Ap + i * 4);
        bv[i] = *(const float4*)(Wp + i * 4);
    }

    for (int k0 = 0; k0 < K; k0 += 32) {
        __syncthreads();
#pragma unroll
        for (int i = 0; i < 4; i++) {
            const float* a4 = (const float*)&av[i];
            const float* b4 = (const float*)&bv[i];
#pragma unroll
            for (int j = 0; j < 4; j++) {
                As[lk + i * 4 + j][lr] = __uint_as_float(f2tf(a4[j]));
                Bs[lk + i * 4 + j][lr] = __uint_as_float(f2tf(b4[j]));
            }
        }
        __syncthreads();
        if (k0 + 32 < K) {                     // prefetch next chunk under MMAs
#pragma unroll
            for (int i = 0; i < 4; i++) {
                av[i] = *(const float4*)(Ap + k0 + 32 + i * 4);
                bv[i] = *(const float4*)(Wp + k0 + 32 + i * 4);
            }
        }

#pragma unroll
        for (int kk = 0; kk < 32; kk += 8) {
            uint32_t a[2][4];
#pragma unroll
            for (int mi = 0; mi < 2; mi++) {
                int m = wm * 32 + mi * 16 + qid;
                a[mi][0] = __float_as_uint(As[kk + qt][m]);
                a[mi][1] = __float_as_uint(As[kk + qt][m + 8]);
                a[mi][2] = __float_as_uint(As[kk + qt + 4][m]);
                a[mi][3] = __float_as_uint(As[kk + qt + 4][m + 8]);
            }
#pragma unroll
            for (int f = 0; f < 8; f++) {
                int n = wn * 64 + f * 8 + qid;
                uint32_t b0 = __float_as_uint(Bs[kk + qt][n]);
                uint32_t b1 = __float_as_uint(Bs[kk + qt + 4][n]);
                mma_tf32(acc[0][f], a[0][0], a[0][1], a[0][2], a[0][3], b0, b1);
                mma_tf32(acc[1][f], a[1][0], a[1][1], a[1][2], a[1][3], b0, b1);
            }
        }
    }

    // LoRA rank-8: acc += scale * XA[row,:] . LB[col,:]
    int r0[2], r1[2];
#pragma unroll
    for (int mi = 0; mi < 2; mi++) {
        r0[mi] = bm + wm * 32 + mi * 16 + qid;
        r1[mi] = r0[mi] + 8;
    }
#pragma unroll
    for (int rr = 0; rr < LORA_R; rr++) {
        float xa0[2], xa1[2];
#pragma unroll
        for (int mi = 0; mi < 2; mi++) {
            xa0[mi] = XA[(size_t)r0[mi] * LORA_R + rr] * LORA_SCALE_C;
            xa1[mi] = XA[(size_t)r1[mi] * LORA_R + rr] * LORA_SCALE_C;
        }
#pragma unroll
        for (int f = 0; f < 8; f++) {
            int c0 = bn + wn * 64 + f * 8 + 2 * qt;
            float lb0 = LB[(size_t)c0 * LORA_R + rr];
            float lb1 = LB[(size_t)(c0 + 1) * LORA_R + rr];
#pragma unroll
            for (int mi = 0; mi < 2; mi++) {
                acc[mi][f][0] += xa0[mi] * lb0;
                acc[mi][f][1] += xa0[mi] * lb1;
                acc[mi][f][2] += xa1[mi] * lb0;
                acc[mi][f][3] += xa1[mi] * lb1;
            }
        }
    }
    if (hasBias) {
#pragma unroll
        for (int f = 0; f < 8; f++) {
            int c0 = bn + wn * 64 + f * 8 + 2 * qt;
            float b0 = bias[c0], b1 = bias[c0 + 1];
#pragma unroll
            for (int mi = 0; mi < 2; mi++) {
                acc[mi][f][0] += b0; acc[mi][f][1] += b1;
                acc[mi][f][2] += b0; acc[mi][f][3] += b1;
            }
        }
    }
#pragma unroll
    for (int mi = 0; mi < 2; mi++)
#pragma unroll
        for (int f = 0; f < 8; f++) {
            int c0 = bn + wn * 64 + f * 8 + 2 * qt;
            *(float2*)(C + (size_t)r0[mi] * N + c0) = make_float2(acc[mi][f][0], acc[mi][f][1]);
            *(float2*)(C + (size_t)r1[mi] * N + c0) = make_float2(acc[mi][f][2], acc[mi][f][3]);
        }
}

// ---------------- RoPE in-place on q,k in g_qkv [B,S,3,H,hd] ----------------
__global__ void rope_kernel(float* __restrict__ qkv) {
    int t = blockIdx.x * blockDim.x + threadIdx.x;
    int i = t & 31;
    int h = (t >> 5) & 15;
    int s = (t >> 9) & 2047;
    int b = t >> 20;
    float inv_freq = expf(-(float)i * (logf(10000.f) / 32.f));
    float ang = (float)s * inv_freq;
    float sn, cs;
    sincosf(ang, &sn, &cs);
    size_t base = ((size_t)(b * SEQ + s) * 3) * D_EMBED + h * HDIM + i;
    float q0 = qkv[base], q1 = qkv[base + 32];
    qkv[base]      = q0 * cs - q1 * sn;
    qkv[base + 32] = q1 * cs + q0 * sn;
    size_t kb = base + D_EMBED;
    float k0 = qkv[kb], k1 = qkv[kb + 32];
    qkv[kb]      = k0 * cs - k1 * sn;
    qkv[kb + 32] = k1 * cs + k0 * sn;
}

// ---------------- TF32 causal flash attention ----------------
// Br=128, Bc=64, hd=64; 256 threads = 8 warps, 16 q-rows per warp.
__global__ __launch_bounds__(256) void flash_tf32(const float* __restrict__ qkv,
                                                  float* __restrict__ out) {
    extern __shared__ float sm[];
    float* Kt = sm;               // [64 d][72]   Kt[d*72 + key] (tf32 bits)
    float* Vs = sm + 64 * 72;     // [64 key][72] Vs[key*72 + d] (tf32 bits)
    float* Ps = sm + 128 * 72;    // per-warp [16][68] P staging (tf32 bits)

    int qb = (int)gridDim.x - 1 - (int)blockIdx.x;   // heavy blocks first
    int bh = blockIdx.y;
    int b = bh >> 4, h = bh & 15;
    int q0 = qb * 128;
    int tid = threadIdx.x, warp = tid >> 5, lane = tid & 31;
    int qid = lane >> 2, qt = lane & 3;
    float* Pw = Ps + warp * 16 * 68;

    // ---- stage Q (128 rows, raw fp32) in Kt∪Vs area, then extract A frags (scaled, tf32)
    {
        int r = tid >> 1, half = tid & 1;
        const float* qp = qkv + ((size_t)(b * SEQ + q0 + r) * 3) * D_EMBED + h * HDIM + half * 32;
        float* dst = sm + r * 72 + half * 32;
#pragma unroll
        for (int i = 0; i < 8; i++)
            *(float4*)(dst + i * 4) = *(const float4*)(qp + i * 4);
    }
    __syncthreads();
    uint32_t qa[8][4];
    {
        int m0 = warp * 16 + qid, m1 = m0 + 8;
        const float sc = 0.125f;  // fold hd^-0.5 into Q
#pragma unroll
        for (int kk = 0; kk < 8; kk++) {
            qa[kk][0] = f2tf(sc * sm[m0 * 72 + kk * 8 + qt]);
            qa[kk][1] = f2tf(sc * sm[m1 * 72 + kk * 8 + qt]);
            qa[kk][2] = f2tf(sc * sm[m0 * 72 + kk * 8 + qt + 4]);
            qa[kk][3] = f2tf(sc * sm[m1 * 72 + kk * 8 + qt + 4]);
        }
    }

    float m0r = -1e30f, m1r = -1e30f, l0 = 0.f, l1 = 0.f;
    float o[8][4];
#pragma unroll
    for (int f = 0; f < 8; f++)
#pragma unroll
        for (int c = 0; c < 4; c++) o[f][c] = 0.f;

    int gq0 = q0 + warp * 16 + qid;      // global q rows owned by this thread
    int gq1 = gq0 + 8;
    int wrow0 = q0 + warp * 16;          // smallest q row in warp

    int ntiles = 2 * qb + 2;
    for (int jt = 0; jt < ntiles; jt++) {
        __syncthreads();   // protect Kt/Vs (Q staging / prev tile readers)
        {
            int kr = tid >> 2, qd = (tid & 3) * 16;
            const float* kp = qkv + ((size_t)(b * SEQ + jt * 64 + kr) * 3 + 1) * D_EMBED + h * HDIM + qd;
            const float* vp = qkv + ((size_t)(b * SEQ + jt * 64 + kr) * 3 + 2) * D_EMBED + h * HDIM + qd;
#pragma unroll
            for (int i = 0; i < 4; i++) {
                int d = qd + i * 4;
                float4 kv = *(const float4*)(kp + i * 4);
                Kt[(d + 0) * 72 + kr] = __uint_as_float(f2tf(kv.x));
                Kt[(d + 1) * 72 + kr] = __uint_as_float(f2tf(kv.y));
                Kt[(d + 2) * 72 + kr] = __uint_as_float(f2tf(kv.z));
                Kt[(d + 3) * 72 + kr] = __uint_as_float(f2tf(kv.w));
                float4 vv = *(const float4*)(vp + i * 4);
                float4 vc;
                vc.x = __uint_as_float(f2tf(vv.x));
                vc.y = __uint_as_float(f2tf(vv.y));
                vc.z = __uint_as_float(f2tf(vv.z));
                vc.w = __uint_as_float(f2tf(vv.w));
                *(float4*)(Vs + kr * 72 + d) = vc;
            }
        }
        __syncthreads();

        if (jt * 64 > wrow0 + 15) continue;   // tile fully masked for this warp

        // ---- S = Q K^T (per warp: 16 x 64)
        float s[8][4];
#pragma unroll
        for (int f = 0; f < 8; f++)
#pragma unroll
            for (int c = 0; c < 4; c++) s[f][c] = 0.f;
#pragma unroll
        for (int kk = 0; kk < 8; kk++) {
#pragma unroll
            for (int f = 0; f < 8; f++) {
                uint32_t b0 = __float_as_uint(Kt[(kk * 8 + qt) * 72 + f * 8 + qid]);
                uint32_t b1 = __float_as_uint(Kt[(kk * 8 + qt + 4) * 72 + f * 8 + qid]);
                mma_tf32(s[f], qa[kk][0], qa[kk][1], qa[kk][2], qa[kk][3], b0, b1);
            }
        }

        // ---- causal mask (only when tile reaches past warp's smallest row)
        if (jt * 64 + 63 > wrow0) {
#pragma unroll
            for (int f = 0; f < 8; f++) {
                int lc = jt * 64 + f * 8 + 2 * qt;
                if (lc > gq0)     s[f][0] = -1e30f;
                if (lc + 1 > gq0) s[f][1] = -1e30f;
                if (lc > gq1)     s[f][2] = -1e30f;
                if (lc + 1 > gq1) s[f][3] = -1e30f;
            }
        }

        // ---- online softmax (rows are quad-shared)
        float rm0 = -1e30f, rm1 = -1e30f;
#pragma unroll
        for (int f = 0; f < 8; f++) {
            rm0 = fmaxf(rm0, fmaxf(s[f][0], s[f][1]));
            rm1 = fmaxf(rm1, fmaxf(s[f][2], s[f][3]));
        }
        rm0 = fmaxf(rm0, __shfl_xor_sync(0xffffffffu, rm0, 1));
        rm0 = fmaxf(rm0, __shfl_xor_sync(0xffffffffu, rm0, 2));
        rm1 = fmaxf(rm1, __shfl_xor_sync(0xffffffffu, rm1, 1));
        rm1 = fmaxf(rm1, __shfl_xor_sync(0xffffffffu, rm1, 2));

        float mn0 = fmaxf(m0r, rm0), mn1 = fmaxf(m1r, rm1);
        float al0 = __expf(m0r - mn0), al1 = __expf(m1r - mn1);
        float rs0 = 0.f, rs1 = 0.f;
#pragma unroll
        for (int f = 0; f < 8; f++) {
            s[f][0] = __expf(s[f][0] - mn0);
            s[f][1] = __expf(s[f][1] - mn0);
            s[f][2] = __expf(s[f][2] - mn1);
            s[f][3] = __expf(s[f][3] - mn1);
            rs0 += s[f][0] + s[f][1];
            rs1 += s[f][2] + s[f][3];
        }
        rs0 += __shfl_xor_sync(0xffffffffu, rs0, 1);
        rs0 += __shfl_xor_sync(0xffffffffu, rs0, 2);
        rs1 += __shfl_xor_sync(0xffffffffu, rs1, 1);
        rs1 += __shfl_xor_sync(0xffffffffu, rs1, 2);
        l0 = l0 * al0 + rs0;
        l1 = l1 * al1 + rs1;
        m0r = mn0; m1r = mn1;
#pragma unroll
        for (int f = 0; f < 8; f++) {
            o[f][0] *= al0; o[f][1] *= al0;
            o[f][2] *= al1; o[f][3] *= al1;
        }

        // ---- stage P (tf32) in per-warp smem, then PV mma into O
        __syncwarp();
#pragma unroll
        for (int f = 0; f < 8; f++) {
            float2 p0 = make_float2(__uint_as_float(f2tf(s[f][0])), __uint_as_float(f2tf(s[f][1])));
            float2 p1 = make_float2(__uint_as_float(f2tf(s[f][2])), __uint_as_float(f2tf(s[f][3])));
            *(float2*)(Pw + qid * 68 + f * 8 + 2 * qt) = p0;
            *(float2*)(Pw + (qid + 8) * 68 + f * 8 + 2 * qt) = p1;
        }
        __syncwarp();
#pragma unroll
        for (int kk = 0; kk < 8; kk++) {
            uint32_t pa0 = __float_as_uint(Pw[qid * 68 + kk * 8 + qt]);
            uint32_t pa1 = __float_as_uint(Pw[(qid + 8) * 68 + kk * 8 + qt]);
            uint32_t pa2 = __float_as_uint(Pw[qid * 68 + kk * 8 + qt + 4]);
            uint32_t pa3 = __float_as_uint(Pw[(qid + 8) * 68 + kk * 8 + qt + 4]);
#pragma unroll
            for (int f = 0; f < 8; f++) {
                uint32_t b0 = __float_as_uint(Vs[(kk * 8 + qt) * 72 + f * 8 + qid]);
                uint32_t b1 = __float_as_uint(Vs[(kk * 8 + qt + 4) * 72 + f * 8 + qid]);
                mma_tf32(o[f], pa0, pa1, pa2, pa3, b0, b1);
            }
        }
    }

    // ---- epilogue: normalize, write [B,S,H*hd]
    float inv0 = 1.f / l0, inv1 = 1.f / l1;
    size_t ro = (size_t)(b * SEQ + gq0) * D_EMBED + h * HDIM;
#pragma unroll
    for (int f = 0; f < 8; f++) {
        *(float2*)(out + ro + f * 8 + 2 * qt) =
            make_float2(o[f][0] * inv0, o[f][1] * inv0);
        *(float2*)(out + ro + 8 * D_EMBED + f * 8 + 2 * qt) =
            make_float2(o[f][2] * inv1, o[f][3] * inv1);
    }
}

// ---------------- launcher ----------------
extern "C" void kernel_launch(void* const* d_in, const int* in_sizes, int n_in,
                              void* d_out, int out_size) {
    const float* x     = (const float*)d_in[0];
    const float* Wqkv  = (const float*)d_in[1];
    const float* Aqkv  = (const float*)d_in[2];
    const float* Bqkv  = (const float*)d_in[3];
    const float* Wproj = (const float*)d_in[4];
    const float* bproj = (const float*)d_in[5];
    const float* Aproj = (const float*)d_in[6];
    const float* Bproj = (const float*)d_in[7];

    float *qkv, *attn, *xa;
    cudaGetSymbolAddress((void**)&qkv,  g_qkv);
    cudaGetSymbolAddress((void**)&attn, g_attn);
    cudaGetSymbolAddress((void**)&xa,   g_xa);

    // 1) LoRA-A for qkv
    lora_a_kernel<<<NTOK / 8, 256>>>(x, Aqkv, xa);
    // 2) QKV GEMM + LoRA-B (tf32 tensor cores)
    gemm_tf32_lora<<<dim3(3 * D_EMBED / 128, NTOK / 128), 256>>>(
        x, Wqkv, xa, Bqkv, nullptr, qkv, NTOK, 3 * D_EMBED, D_EMBED, 0);
    // 3) RoPE on q,k
    rope_kernel<<<(BATCH * SEQ * NHEAD * 32) / 256, 256>>>(qkv);
    // 4) causal flash attention (tf32 tensor cores), Br=128
    int smem = (128 * 72 + 8 * 16 * 68) * (int)sizeof(float);
    cudaFuncSetAttribute(flash_tf32,
                         cudaFuncAttributeMaxDynamicSharedMemorySize, smem);
    flash_tf32<<<dim3(SEQ / 128, BATCH * NHEAD), 256, smem>>>(qkv, attn);
    // 5) LoRA-A for proj
    lora_a_kernel<<<NTOK / 8, 256>>>(attn, Aproj, xa);
    // 6) output projection + bias + LoRA-B -> d_out
    gemm_tf32_lora<<<dim3(D_EMBED / 128, NTOK / 128), 256>>>(
        attn, Wproj, xa, Bproj, bproj, (float*)d_out, NTOK, D_EMBED, D_EMBED, 1);
}

// round 6
// speedup vs baseline: 2.8681x; 1.1030x over previous
#include <cuda_runtime.h>
#include <math.h>
#include <stdint.h>

#define D_EMBED 1024
#define SEQ     2048
#define BATCH   2
#define NHEAD   16
#define HDIM    64
#define NTOK    (BATCH * SEQ)      // 4096
#define LORA_R  8
#define LORA_SCALE_C 2.0f          // alpha/r = 16/8

// ---------------- scratch (no allocations allowed) ----------------
__device__ float g_qkv[(size_t)NTOK * 3 * D_EMBED];   // [B,S,3,H,hd]
__device__ float g_attn[(size_t)NTOK * D_EMBED];      // attention out [B,S,D]
__device__ float g_xa[(size_t)NTOK * LORA_R];         // x @ A^T

// ---------------- helpers ----------------
__device__ __forceinline__ uint32_t f2tf(float x) {
    uint32_t u; asm("cvt.rna.tf32.f32 %0, %1;" : "=r"(u) : "f"(x)); return u;
}
__device__ __forceinline__ void mma_tf32(float c[4],
                                         uint32_t a0, uint32_t a1, uint32_t a2, uint32_t a3,
                                         uint32_t b0, uint32_t b1) {
    asm volatile(
        "mma.sync.aligned.m16n8k8.row.col.f32.tf32.tf32.f32 "
        "{%0,%1,%2,%3}, {%4,%5,%6,%7}, {%8,%9}, {%0,%1,%2,%3};"
        : "+f"(c[0]), "+f"(c[1]), "+f"(c[2]), "+f"(c[3])
        : "r"(a0), "r"(a1), "r"(a2), "r"(a3), "r"(b0), "r"(b1));
}
__device__ __forceinline__ void cp16(float* dst_smem, const float* src) {
    uint32_t d = (uint32_t)__cvta_generic_to_shared(dst_smem);
    asm volatile("cp.async.cg.shared.global [%0], [%1], 16;" :: "r"(d), "l"(src));
}
#define CP_COMMIT() asm volatile("cp.async.commit_group;")
#define CP_WAIT0()  asm volatile("cp.async.wait_group 0;")

// ---------------- LoRA A projection: out[M,8] = X[M,K] @ Aw[8,K]^T ----------------
__global__ void lora_a_kernel(const float* __restrict__ X,
                              const float* __restrict__ Aw,
                              float* __restrict__ out) {
    __shared__ float As[LORA_R * D_EMBED];
    for (int i = threadIdx.x; i < LORA_R * D_EMBED; i += blockDim.x) As[i] = Aw[i];
    __syncthreads();
    int warp = threadIdx.x >> 5, lane = threadIdx.x & 31;
    int row = blockIdx.x * 8 + warp;
    const float* xr = X + (size_t)row * D_EMBED;
    float s[LORA_R];
#pragma unroll
    for (int r = 0; r < LORA_R; r++) s[r] = 0.f;
    for (int k = lane; k < D_EMBED; k += 32) {
        float xv = xr[k];
#pragma unroll
        for (int r = 0; r < LORA_R; r++) s[r] += xv * As[r * D_EMBED + k];
    }
#pragma unroll
    for (int off = 16; off > 0; off >>= 1) {
#pragma unroll
        for (int r = 0; r < LORA_R; r++) s[r] += __shfl_xor_sync(0xffffffffu, s[r], off);
    }
    if (lane == 0) {
#pragma unroll
        for (int r = 0; r < LORA_R; r++) out[(size_t)row * LORA_R + r] = s[r];
    }
}

// ---------------- TF32 GEMM (NT), cp.async double-buffered ----------------
// 128x128 tile, BK=32, 256 threads = 8 warps (4m x 2n), warp tile 32x64.
// smem: As[2][128][36], Bs[2][128][36] raw fp32 rows; cvt to tf32 at frag load.
#define GP 36
__global__ __launch_bounds__(256) void gemm_tf32_lora(
    const float* __restrict__ A, const float* __restrict__ W,
    const float* __restrict__ XA, const float* __restrict__ LB,
    const float* __restrict__ bias, float* __restrict__ C,
    int M, int N, int K, int hasBias) {
    extern __shared__ float smg[];
    float* As = smg;                    // [2][128*GP]
    float* Bs = smg + 2 * 128 * GP;     // [2][128*GP]

    int bm = blockIdx.y * 128, bn = blockIdx.x * 128;
    int tid = threadIdx.x;
    int warp = tid >> 5, lane = tid & 31;
    int wm = warp >> 1, wn = warp & 1;
    int qid = lane >> 2, qt = lane & 3;

    float acc[2][8][4];
#pragma unroll
    for (int mi = 0; mi < 2; mi++)
#pragma unroll
        for (int f = 0; f < 8; f++)
#pragma unroll
            for (int c = 0; c < 4; c++) acc[mi][f][c] = 0.f;

    // copy of one K-chunk (A+B tiles) into buffer `buf`
    auto issue_tiles = [&](int k0, int buf) {
#pragma unroll
        for (int c = tid; c < 1024; c += 256) {     // 4 chunks/thread for A
            int row = c >> 3, off = (c & 7) * 4;
            cp16(As + buf * 128 * GP + row * GP + off,
                 A + (size_t)(bm + row) * K + k0 + off);
        }
#pragma unroll
        for (int c = tid; c < 1024; c += 256) {     // 4 chunks/thread for B
            int row = c >> 3, off = (c & 7) * 4;
            cp16(Bs + buf * 128 * GP + row * GP + off,
                 W + (size_t)(bn + row) * K + k0 + off);
        }
    };

    issue_tiles(0, 0);
    CP_COMMIT();

    int niter = K >> 5;
    for (int it = 0; it < niter; it++) {
        int buf = it & 1;
        CP_WAIT0();
        __syncthreads();
        if (it + 1 < niter) { issue_tiles((it + 1) << 5, buf ^ 1); CP_COMMIT(); }

        const float* Ab = As + buf * 128 * GP;
        const float* Bb = Bs + buf * 128 * GP;
#pragma unroll
        for (int kk = 0; kk < 32; kk += 8) {
            uint32_t a[2][4];
#pragma unroll
            for (int mi = 0; mi < 2; mi++) {
                int m = wm * 32 + mi * 16 + qid;
                a[mi][0] = f2tf(Ab[m * GP + kk + qt]);
                a[mi][1] = f2tf(Ab[(m + 8) * GP + kk + qt]);
                a[mi][2] = f2tf(Ab[m * GP + kk + qt + 4]);
                a[mi][3] = f2tf(Ab[(m + 8) * GP + kk + qt + 4]);
            }
#pragma unroll
            for (int f = 0; f < 8; f++) {
                int n = wn * 64 + f * 8 + qid;
                uint32_t b0 = f2tf(Bb[n * GP + kk + qt]);
                uint32_t b1 = f2tf(Bb[n * GP + kk + qt + 4]);
                mma_tf32(acc[0][f], a[0][0], a[0][1], a[0][2], a[0][3], b0, b1);
                mma_tf32(acc[1][f], a[1][0], a[1][1], a[1][2], a[1][3], b0, b1);
            }
        }
        __syncthreads();   // everyone done with buf before it is refilled
    }

    // LoRA rank-8: acc += scale * XA[row,:] . LB[col,:]
    int r0[2], r1[2];
#pragma unroll
    for (int mi = 0; mi < 2; mi++) {
        r0[mi] = bm + wm * 32 + mi * 16 + qid;
        r1[mi] = r0[mi] + 8;
    }
#pragma unroll
    for (int rr = 0; rr < LORA_R; rr++) {
        float xa0[2], xa1[2];
#pragma unroll
        for (int mi = 0; mi < 2; mi++) {
            xa0[mi] = XA[(size_t)r0[mi] * LORA_R + rr] * LORA_SCALE_C;
            xa1[mi] = XA[(size_t)r1[mi] * LORA_R + rr] * LORA_SCALE_C;
        }
#pragma unroll
        for (int f = 0; f < 8; f++) {
            int c0 = bn + wn * 64 + f * 8 + 2 * qt;
            float lb0 = LB[(size_t)c0 * LORA_R + rr];
            float lb1 = LB[(size_t)(c0 + 1) * LORA_R + rr];
#pragma unroll
            for (int mi = 0; mi < 2; mi++) {
                acc[mi][f][0] += xa0[mi] * lb0;
                acc[mi][f][1] += xa0[mi] * lb1;
                acc[mi][f][2] += xa1[mi] * lb0;
                acc[mi][f][3] += xa1[mi] * lb1;
            }
        }
    }
    if (hasBias) {
#pragma unroll
        for (int f = 0; f < 8; f++) {
            int c0 = bn + wn * 64 + f * 8 + 2 * qt;
            float b0 = bias[c0], b1 = bias[c0 + 1];
#pragma unroll
            for (int mi = 0; mi < 2; mi++) {
                acc[mi][f][0] += b0; acc[mi][f][1] += b1;
                acc[mi][f][2] += b0; acc[mi][f][3] += b1;
            }
        }
    }
#pragma unroll
    for (int mi = 0; mi < 2; mi++)
#pragma unroll
        for (int f = 0; f < 8; f++) {
            int c0 = bn + wn * 64 + f * 8 + 2 * qt;
            *(float2*)(C + (size_t)r0[mi] * N + c0) = make_float2(acc[mi][f][0], acc[mi][f][1]);
            *(float2*)(C + (size_t)r1[mi] * N + c0) = make_float2(acc[mi][f][2], acc[mi][f][3]);
        }
}

// ---------------- RoPE in-place on q,k in g_qkv [B,S,3,H,hd] ----------------
__global__ void rope_kernel(float* __restrict__ qkv) {
    int t = blockIdx.x * blockDim.x + threadIdx.x;
    int i = t & 31;
    int h = (t >> 5) & 15;
    int s = (t >> 9) & 2047;
    int b = t >> 20;
    float inv_freq = expf(-(float)i * (logf(10000.f) / 32.f));
    float ang = (float)s * inv_freq;
    float sn, cs;
    sincosf(ang, &sn, &cs);
    size_t base = ((size_t)(b * SEQ + s) * 3) * D_EMBED + h * HDIM + i;
    float q0 = qkv[base], q1 = qkv[base + 32];
    qkv[base]      = q0 * cs - q1 * sn;
    qkv[base + 32] = q1 * cs + q0 * sn;
    size_t kb = base + D_EMBED;
    float k0 = qkv[kb], k1 = qkv[kb + 32];
    qkv[kb]      = k0 * cs - k1 * sn;
    qkv[kb + 32] = k1 * cs + k0 * sn;
}

// ---------------- TF32 causal flash attention, cp.async double-buffered ----------------
// Br=128, Bc=64, hd=64; 256 threads = 8 warps, 16 q-rows per warp.
// smem: Ks[2][64][76] raw K rows, Vs[2][64][76] raw V rows, Ps per-warp [16][68].
#define FP 76
__global__ __launch_bounds__(256, 2) void flash_tf32(const float* __restrict__ qkv,
                                                     float* __restrict__ out) {
    extern __shared__ float sm[];
    float* Ks = sm;                       // [2][64*FP]
    float* Vs = sm + 2 * 64 * FP;         // [2][64*FP]
    float* Ps = sm + 4 * 64 * FP;         // 8 warps x [16][68]

    int qb = (int)gridDim.x - 1 - (int)blockIdx.x;   // heavy blocks first
    int bh = blockIdx.y;
    int b = bh >> 4, h = bh & 15;
    int q0 = qb * 128;
    int tid = threadIdx.x, warp = tid >> 5, lane = tid & 31;
    int qid = lane >> 2, qt = lane & 3;
    float* Pw = Ps + warp * 16 * 68;

    int gq0 = q0 + warp * 16 + qid;      // global q rows owned by this thread
    int gq1 = gq0 + 8;
    int wrow0 = q0 + warp * 16;          // smallest q row in warp
    int ntiles = 2 * qb + 2;

    // issue cp.async copies for K/V tile jt into buffer `buf`
    auto issue_kv = [&](int jt, int buf) {
        const float* kbase = qkv + ((size_t)(b * SEQ + jt * 64) * 3 + 1) * D_EMBED + h * HDIM;
        const float* vbase = kbase + D_EMBED;
#pragma unroll
        for (int c = tid; c < 1024; c += 256) {      // 4 chunks/thread for K
            int row = c >> 4, off = (c & 15) * 4;
            cp16(Ks + buf * 64 * FP + row * FP + off, kbase + (size_t)row * 3 * D_EMBED + off);
        }
#pragma unroll
        for (int c = tid; c < 1024; c += 256) {      // 4 chunks/thread for V
            int row = c >> 4, off = (c & 15) * 4;
            cp16(Vs + buf * 64 * FP + row * FP + off, vbase + (size_t)row * 3 * D_EMBED + off);
        }
    };

    issue_kv(0, 0);
    CP_COMMIT();

    // ---- Q fragments straight from gmem (scaled, tf32)
    uint32_t qa[8][4];
    {
        const float sc = 0.125f;  // fold hd^-0.5 into Q
        const float* qp0 = qkv + ((size_t)(b * SEQ + gq0) * 3) * D_EMBED + h * HDIM;
        const float* qp1 = qp0 + (size_t)8 * 3 * D_EMBED;
#pragma unroll
        for (int kk = 0; kk < 8; kk++) {
            qa[kk][0] = f2tf(sc * __ldg(qp0 + kk * 8 + qt));
            qa[kk][1] = f2tf(sc * __ldg(qp1 + kk * 8 + qt));
            qa[kk][2] = f2tf(sc * __ldg(qp0 + kk * 8 + qt + 4));
            qa[kk][3] = f2tf(sc * __ldg(qp1 + kk * 8 + qt + 4));
        }
    }

    float m0r = -1e30f, m1r = -1e30f, l0 = 0.f, l1 = 0.f;
    float o[8][4];
#pragma unroll
    for (int f = 0; f < 8; f++)
#pragma unroll
        for (int c = 0; c < 4; c++) o[f][c] = 0.f;

    for (int jt = 0; jt < ntiles; jt++) {
        int buf = jt & 1;
        CP_WAIT0();
        __syncthreads();                 // buf visible to all; prev compute done
        if (jt + 1 < ntiles) { issue_kv(jt + 1, buf ^ 1); CP_COMMIT(); }

        if (jt * 64 > wrow0 + 15) continue;   // tile fully masked for this warp

        const float* Kb = Ks + buf * 64 * FP;
        const float* Vb = Vs + buf * 64 * FP;

        // ---- S = Q K^T (per warp: 16 x 64)
        float s[8][4];
#pragma unroll
        for (int f = 0; f < 8; f++)
#pragma unroll
            for (int c = 0; c < 4; c++) s[f][c] = 0.f;
#pragma unroll
        for (int kk = 0; kk < 8; kk++) {
#pragma unroll
            for (int f = 0; f < 8; f++) {
                uint32_t b0 = f2tf(Kb[(f * 8 + qid) * FP + kk * 8 + qt]);
                uint32_t b1 = f2tf(Kb[(f * 8 + qid) * FP + kk * 8 + qt + 4]);
                mma_tf32(s[f], qa[kk][0], qa[kk][1], qa[kk][2], qa[kk][3], b0, b1);
            }
        }

        // ---- causal mask (only when tile reaches past warp's smallest row)
        if (jt * 64 + 63 > wrow0) {
#pragma unroll
            for (int f = 0; f < 8; f++) {
                int lc = jt * 64 + f * 8 + 2 * qt;
                if (lc > gq0)     s[f][0] = -1e30f;
                if (lc + 1 > gq0) s[f][1] = -1e30f;
                if (lc > gq1)     s[f][2] = -1e30f;
                if (lc + 1 > gq1) s[f][3] = -1e30f;
            }
        }

        // ---- online softmax (rows are quad-shared)
        float rm0 = -1e30f, rm1 = -1e30f;
#pragma unroll
        for (int f = 0; f < 8; f++) {
            rm0 = fmaxf(rm0, fmaxf(s[f][0], s[f][1]));
            rm1 = fmaxf(rm1, fmaxf(s[f][2], s[f][3]));
        }
        rm0 = fmaxf(rm0, __shfl_xor_sync(0xffffffffu, rm0, 1));
        rm0 = fmaxf(rm0, __shfl_xor_sync(0xffffffffu, rm0, 2));
        rm1 = fmaxf(rm1, __shfl_xor_sync(0xffffffffu, rm1, 1));
        rm1 = fmaxf(rm1, __shfl_xor_sync(0xffffffffu, rm1, 2));

        float mn0 = fmaxf(m0r, rm0), mn1 = fmaxf(m1r, rm1);
        float al0 = __expf(m0r - mn0), al1 = __expf(m1r - mn1);
        float rs0 = 0.f, rs1 = 0.f;
#pragma unroll
        for (int f = 0; f < 8; f++) {
            s[f][0] = __expf(s[f][0] - mn0);
            s[f][1] = __expf(s[f][1] - mn0);
            s[f][2] = __expf(s[f][2] - mn1);
            s[f][3] = __expf(s[f][3] - mn1);
            rs0 += s[f][0] + s[f][1];
            rs1 += s[f][2] + s[f][3];
        }
        rs0 += __shfl_xor_sync(0xffffffffu, rs0, 1);
        rs0 += __shfl_xor_sync(0xffffffffu, rs0, 2);
        rs1 += __shfl_xor_sync(0xffffffffu, rs1, 1);
        rs1 += __shfl_xor_sync(0xffffffffu, rs1, 2);
        l0 = l0 * al0 + rs0;
        l1 = l1 * al1 + rs1;
        m0r = mn0; m1r = mn1;
#pragma unroll
        for (int f = 0; f < 8; f++) {
            o[f][0] *= al0; o[f][1] *= al0;
            o[f][2] *= al1; o[f][3] *= al1;
        }

        // ---- stage P (tf32 bits) in per-warp smem, then PV mma into O
        __syncwarp();
#pragma unroll
        for (int f = 0; f < 8; f++) {
            float2 p0 = make_float2(__uint_as_float(f2tf(s[f][0])), __uint_as_float(f2tf(s[f][1])));
            float2 p1 = make_float2(__uint_as_float(f2tf(s[f][2])), __uint_as_float(f2tf(s[f][3])));
            *(float2*)(Pw + qid * 68 + f * 8 + 2 * qt) = p0;
            *(float2*)(Pw + (qid + 8) * 68 + f * 8 + 2 * qt) = p1;
        }
        __syncwarp();
#pragma unroll
        for (int kk = 0; kk < 8; kk++) {
            uint32_t pa0 = __float_as_uint(Pw[qid * 68 + kk * 8 + qt]);
            uint32_t pa1 = __float_as_uint(Pw[(qid + 8) * 68 + kk * 8 + qt]);
            uint32_t pa2 = __float_as_uint(Pw[qid * 68 + kk * 8 + qt + 4]);
            uint32_t pa3 = __float_as_uint(Pw[(qid + 8) * 68 + kk * 8 + qt + 4]);
#pragma unroll
            for (int f = 0; f < 8; f++) {
                uint32_t b0 = f2tf(Vb[(kk * 8 + qt) * FP + f * 8 + qid]);
                uint32_t b1 = f2tf(Vb[(kk * 8 + qt + 4) * FP + f * 8 + qid]);
                mma_tf32(o[f], pa0, pa1, pa2, pa3, b0, b1);
            }
        }
    }

    // ---- epilogue: normalize, write [B,S,H*hd]
    float inv0 = 1.f / l0, inv1 = 1.f / l1;
    size_t ro = (size_t)(b * SEQ + gq0) * D_EMBED + h * HDIM;
#pragma unroll
    for (int f = 0; f < 8; f++) {
        *(float2*)(out + ro + f * 8 + 2 * qt) =
            make_float2(o[f][0] * inv0, o[f][1] * inv0);
        *(float2*)(out + ro + 8 * D_EMBED + f * 8 + 2 * qt) =
            make_float2(o[f][2] * inv1, o[f][3] * inv1);
    }
}

// ---------------- launcher ----------------
extern "C" void kernel_launch(void* const* d_in, const int* in_sizes, int n_in,
                              void* d_out, int out_size) {
    const float* x     = (const float*)d_in[0];
    const float* Wqkv  = (const float*)d_in[1];
    const float* Aqkv  = (const float*)d_in[2];
    const float* Bqkv  = (const float*)d_in[3];
    const float* Wproj = (const float*)d_in[4];
    const float* bproj = (const float*)d_in[5];
    const float* Aproj = (const float*)d_in[6];
    const float* Bproj = (const float*)d_in[7];

    float *qkv, *attn, *xa;
    cudaGetSymbolAddress((void**)&qkv,  g_qkv);
    cudaGetSymbolAddress((void**)&attn, g_attn);
    cudaGetSymbolAddress((void**)&xa,   g_xa);

    int gsmem = 4 * 128 * GP * (int)sizeof(float);          // 73.7 KB
    cudaFuncSetAttribute(gemm_tf32_lora,
                         cudaFuncAttributeMaxDynamicSharedMemorySize, gsmem);
    int fsmem = (4 * 64 * FP + 8 * 16 * 68) * (int)sizeof(float);  // 112.6 KB
    cudaFuncSetAttribute(flash_tf32,
                         cudaFuncAttributeMaxDynamicSharedMemorySize, fsmem);

    // 1) LoRA-A for qkv
    lora_a_kernel<<<NTOK / 8, 256>>>(x, Aqkv, xa);
    // 2) QKV GEMM + LoRA-B (tf32 tensor cores, cp.async)
    gemm_tf32_lora<<<dim3(3 * D_EMBED / 128, NTOK / 128), 256, gsmem>>>(
        x, Wqkv, xa, Bqkv, nullptr, qkv, NTOK, 3 * D_EMBED, D_EMBED, 0);
    // 3) RoPE on q,k
    rope_kernel<<<(BATCH * SEQ * NHEAD * 32) / 256, 256>>>(qkv);
    // 4) causal flash attention (tf32, cp.async), Br=128
    flash_tf32<<<dim3(SEQ / 128, BATCH * NHEAD), 256, fsmem>>>(qkv, attn);
    // 5) LoRA-A for proj
    lora_a_kernel<<<NTOK / 8, 256>>>(attn, Aproj, xa);
    // 6) output projection + bias + LoRA-B -> d_out
    gemm_tf32_lora<<<dim3(D_EMBED / 128, NTOK / 128), 256, gsmem>>>(
        attn, Wproj, xa, Bproj, bproj, (float*)d_out, NTOK, D_EMBED, D_EMBED, 1);
}

// round 7
// speedup vs baseline: 2.9694x; 1.0353x over previous
#include <cuda_runtime.h>
#include <math.h>
#include <stdint.h>

#define D_EMBED 1024
#define SEQ     2048
#define BATCH   2
#define NHEAD   16
#define HDIM    64
#define NTOK    (BATCH * SEQ)      // 4096
#define LORA_R  8
#define LORA_SCALE_C 2.0f          // alpha/r = 16/8

// ---------------- scratch (no allocations allowed) ----------------
__device__ float g_qkv[(size_t)NTOK * 3 * D_EMBED];   // [B,S,3,H,hd]
__device__ float g_attn[(size_t)NTOK * D_EMBED];      // attention out [B,S,D]
__device__ float g_xa[(size_t)NTOK * LORA_R];         // x @ A^T

// ---------------- helpers ----------------
__device__ __forceinline__ uint32_t f2tf(float x) {
    uint32_t u; asm("cvt.rna.tf32.f32 %0, %1;" : "=r"(u) : "f"(x)); return u;
}
__device__ __forceinline__ void mma_tf32(float c[4],
                                         uint32_t a0, uint32_t a1, uint32_t a2, uint32_t a3,
                                         uint32_t b0, uint32_t b1) {
    asm volatile(
        "mma.sync.aligned.m16n8k8.row.col.f32.tf32.tf32.f32 "
        "{%0,%1,%2,%3}, {%4,%5,%6,%7}, {%8,%9}, {%0,%1,%2,%3};"
        : "+f"(c[0]), "+f"(c[1]), "+f"(c[2]), "+f"(c[3])
        : "r"(a0), "r"(a1), "r"(a2), "r"(a3), "r"(b0), "r"(b1));
}
__device__ __forceinline__ void cp16(float* dst_smem, const float* src) {
    uint32_t d = (uint32_t)__cvta_generic_to_shared(dst_smem);
    asm volatile("cp.async.cg.shared.global [%0], [%1], 16;" :: "r"(d), "l"(src));
}
#define CP_COMMIT() asm volatile("cp.async.commit_group;")
#define CP_WAIT0()  asm volatile("cp.async.wait_group 0;")

// ---------------- LoRA A projection: out[M,8] = X[M,K] @ Aw[8,K]^T ----------------
__global__ void lora_a_kernel(const float* __restrict__ X,
                              const float* __restrict__ Aw,
                              float* __restrict__ out) {
    __shared__ float As[LORA_R * D_EMBED];
    for (int i = threadIdx.x; i < LORA_R * D_EMBED; i += blockDim.x) As[i] = Aw[i];
    __syncthreads();
    int warp = threadIdx.x >> 5, lane = threadIdx.x & 31;
    int row = blockIdx.x * 8 + warp;
    const float* xr = X + (size_t)row * D_EMBED;
    float s[LORA_R];
#pragma unroll
    for (int r = 0; r < LORA_R; r++) s[r] = 0.f;
    for (int k = lane; k < D_EMBED; k += 32) {
        float xv = xr[k];
#pragma unroll
        for (int r = 0; r < LORA_R; r++) s[r] += xv * As[r * D_EMBED + k];
    }
#pragma unroll
    for (int off = 16; off > 0; off >>= 1) {
#pragma unroll
        for (int r = 0; r < LORA_R; r++) s[r] += __shfl_xor_sync(0xffffffffu, s[r], off);
    }
    if (lane == 0) {
#pragma unroll
        for (int r = 0; r < LORA_R; r++) out[(size_t)row * LORA_R + r] = s[r];
    }
}

// ---------------- TF32 GEMM (NT), cp.async double-buffered ----------------
// 128x128 tile, BK=32, 256 threads = 8 warps (4m x 2n), warp tile 32x64.
#define GP 36
__global__ __launch_bounds__(256) void gemm_tf32_lora(
    const float* __restrict__ A, const float* __restrict__ W,
    const float* __restrict__ XA, const float* __restrict__ LB,
    const float* __restrict__ bias, float* __restrict__ C,
    int M, int N, int K, int hasBias) {
    extern __shared__ float smg[];
    float* As = smg;                    // [2][128*GP]
    float* Bs = smg + 2 * 128 * GP;     // [2][128*GP]

    int bm = blockIdx.y * 128, bn = blockIdx.x * 128;
    int tid = threadIdx.x;
    int warp = tid >> 5, lane = tid & 31;
    int wm = warp >> 1, wn = warp & 1;
    int qid = lane >> 2, qt = lane & 3;

    float acc[2][8][4];
#pragma unroll
    for (int mi = 0; mi < 2; mi++)
#pragma unroll
        for (int f = 0; f < 8; f++)
#pragma unroll
            for (int c = 0; c < 4; c++) acc[mi][f][c] = 0.f;

    auto issue_tiles = [&](int k0, int buf) {
#pragma unroll
        for (int c = tid; c < 1024; c += 256) {
            int row = c >> 3, off = (c & 7) * 4;
            cp16(As + buf * 128 * GP + row * GP + off,
                 A + (size_t)(bm + row) * K + k0 + off);
        }
#pragma unroll
        for (int c = tid; c < 1024; c += 256) {
            int row = c >> 3, off = (c & 7) * 4;
            cp16(Bs + buf * 128 * GP + row * GP + off,
                 W + (size_t)(bn + row) * K + k0 + off);
        }
    };

    issue_tiles(0, 0);
    CP_COMMIT();

    int niter = K >> 5;
    for (int it = 0; it < niter; it++) {
        int buf = it & 1;
        CP_WAIT0();
        __syncthreads();
        if (it + 1 < niter) { issue_tiles((it + 1) << 5, buf ^ 1); CP_COMMIT(); }

        const float* Ab = As + buf * 128 * GP;
        const float* Bb = Bs + buf * 128 * GP;
#pragma unroll
        for (int kk = 0; kk < 32; kk += 8) {
            uint32_t a[2][4];
#pragma unroll
            for (int mi = 0; mi < 2; mi++) {
                int m = wm * 32 + mi * 16 + qid;
                a[mi][0] = f2tf(Ab[m * GP + kk + qt]);
                a[mi][1] = f2tf(Ab[(m + 8) * GP + kk + qt]);
                a[mi][2] = f2tf(Ab[m * GP + kk + qt + 4]);
                a[mi][3] = f2tf(Ab[(m + 8) * GP + kk + qt + 4]);
            }
#pragma unroll
            for (int f = 0; f < 8; f++) {
                int n = wn * 64 + f * 8 + qid;
                uint32_t b0 = f2tf(Bb[n * GP + kk + qt]);
                uint32_t b1 = f2tf(Bb[n * GP + kk + qt + 4]);
                mma_tf32(acc[0][f], a[0][0], a[0][1], a[0][2], a[0][3], b0, b1);
                mma_tf32(acc[1][f], a[1][0], a[1][1], a[1][2], a[1][3], b0, b1);
            }
        }
        __syncthreads();
    }

    // LoRA rank-8: acc += scale * XA[row,:] . LB[col,:]
    int r0[2], r1[2];
#pragma unroll
    for (int mi = 0; mi < 2; mi++) {
        r0[mi] = bm + wm * 32 + mi * 16 + qid;
        r1[mi] = r0[mi] + 8;
    }
#pragma unroll
    for (int rr = 0; rr < LORA_R; rr++) {
        float xa0[2], xa1[2];
#pragma unroll
        for (int mi = 0; mi < 2; mi++) {
            xa0[mi] = XA[(size_t)r0[mi] * LORA_R + rr] * LORA_SCALE_C;
            xa1[mi] = XA[(size_t)r1[mi] * LORA_R + rr] * LORA_SCALE_C;
        }
#pragma unroll
        for (int f = 0; f < 8; f++) {
            int c0 = bn + wn * 64 + f * 8 + 2 * qt;
            float lb0 = LB[(size_t)c0 * LORA_R + rr];
            float lb1 = LB[(size_t)(c0 + 1) * LORA_R + rr];
#pragma unroll
            for (int mi = 0; mi < 2; mi++) {
                acc[mi][f][0] += xa0[mi] * lb0;
                acc[mi][f][1] += xa0[mi] * lb1;
                acc[mi][f][2] += xa1[mi] * lb0;
                acc[mi][f][3] += xa1[mi] * lb1;
            }
        }
    }
    if (hasBias) {
#pragma unroll
        for (int f = 0; f < 8; f++) {
            int c0 = bn + wn * 64 + f * 8 + 2 * qt;
            float b0 = bias[c0], b1 = bias[c0 + 1];
#pragma unroll
            for (int mi = 0; mi < 2; mi++) {
                acc[mi][f][0] += b0; acc[mi][f][1] += b1;
                acc[mi][f][2] += b0; acc[mi][f][3] += b1;
            }
        }
    }
#pragma unroll
    for (int mi = 0; mi < 2; mi++)
#pragma unroll
        for (int f = 0; f < 8; f++) {
            int c0 = bn + wn * 64 + f * 8 + 2 * qt;
            *(float2*)(C + (size_t)r0[mi] * N + c0) = make_float2(acc[mi][f][0], acc[mi][f][1]);
            *(float2*)(C + (size_t)r1[mi] * N + c0) = make_float2(acc[mi][f][2], acc[mi][f][3]);
        }
}

// ---------------- RoPE in-place on q,k in g_qkv [B,S,3,H,hd] ----------------
__global__ void rope_kernel(float* __restrict__ qkv) {
    int t = blockIdx.x * blockDim.x + threadIdx.x;
    int i = t & 31;
    int h = (t >> 5) & 15;
    int s = (t >> 9) & 2047;
    int b = t >> 20;
    float inv_freq = expf(-(float)i * (logf(10000.f) / 32.f));
    float ang = (float)s * inv_freq;
    float sn, cs;
    sincosf(ang, &sn, &cs);
    size_t base = ((size_t)(b * SEQ + s) * 3) * D_EMBED + h * HDIM + i;
    float q0 = qkv[base], q1 = qkv[base + 32];
    qkv[base]      = q0 * cs - q1 * sn;
    qkv[base + 32] = q1 * cs + q0 * sn;
    size_t kb = base + D_EMBED;
    float k0 = qkv[kb], k1 = qkv[kb + 32];
    qkv[kb]      = k0 * cs - k1 * sn;
    qkv[kb + 32] = k1 * cs + k0 * sn;
}

// ---------------- TF32 causal flash attention, cp.async double-buffered ----------------
// Br=128, Bc=64, hd=64; 256 threads = 8 warps, 16 q-rows per warp.
// smem: Ks[2][64][72], Vs[2][64][72] raw fp32, Ps per-warp [16][68].
// Total 27136 floats = 108.5 KB -> 2 CTAs/SM.
#define FP 72
__global__ __launch_bounds__(256, 2) void flash_tf32(const float* __restrict__ qkv,
                                                     float* __restrict__ out) {
    extern __shared__ float sm[];
    float* Ks = sm;                       // [2][64*FP]
    float* Vs = sm + 2 * 64 * FP;         // [2][64*FP]
    float* Ps = sm + 4 * 64 * FP;         // 8 warps x [16][68]

    int qb = (int)gridDim.x - 1 - (int)blockIdx.x;   // heavy blocks first
    int bh = blockIdx.y;
    int b = bh >> 4, h = bh & 15;
    int q0 = qb * 128;
    int tid = threadIdx.x, warp = tid >> 5, lane = tid & 31;
    int qid = lane >> 2, qt = lane & 3;
    float* Pw = Ps + warp * 16 * 68;

    int gq0 = q0 + warp * 16 + qid;      // global q rows owned by this thread
    int gq1 = gq0 + 8;
    int wrow0 = q0 + warp * 16;          // smallest q row in warp
    int ntiles = 2 * qb + 2;

    auto issue_kv = [&](int jt, int buf) {
        const float* kbase = qkv + ((size_t)(b * SEQ + jt * 64) * 3 + 1) * D_EMBED + h * HDIM;
        const float* vbase = kbase + D_EMBED;
#pragma unroll
        for (int c = tid; c < 1024; c += 256) {
            int row = c >> 4, off = (c & 15) * 4;
            cp16(Ks + buf * 64 * FP + row * FP + off, kbase + (size_t)row * 3 * D_EMBED + off);
        }
#pragma unroll
        for (int c = tid; c < 1024; c += 256) {
            int row = c >> 4, off = (c & 15) * 4;
            cp16(Vs + buf * 64 * FP + row * FP + off, vbase + (size_t)row * 3 * D_EMBED + off);
        }
    };

    issue_kv(0, 0);
    CP_COMMIT();

    // ---- Q fragments straight from gmem (scaled, tf32)
    uint32_t qa[8][4];
    {
        const float sc = 0.125f;  // fold hd^-0.5 into Q
        const float* qp0 = qkv + ((size_t)(b * SEQ + gq0) * 3) * D_EMBED + h * HDIM;
        const float* qp1 = qp0 + (size_t)8 * 3 * D_EMBED;
#pragma unroll
        for (int kk = 0; kk < 8; kk++) {
            qa[kk][0] = f2tf(sc * __ldg(qp0 + kk * 8 + qt));
            qa[kk][1] = f2tf(sc * __ldg(qp1 + kk * 8 + qt));
            qa[kk][2] = f2tf(sc * __ldg(qp0 + kk * 8 + qt + 4));
            qa[kk][3] = f2tf(sc * __ldg(qp1 + kk * 8 + qt + 4));
        }
    }

    float m0r = -1e30f, m1r = -1e30f, l0 = 0.f, l1 = 0.f;
    float o[8][4];
#pragma unroll
    for (int f = 0; f < 8; f++)
#pragma unroll
        for (int c = 0; c < 4; c++) o[f][c] = 0.f;

    for (int jt = 0; jt < ntiles; jt++) {
        int buf = jt & 1;
        CP_WAIT0();
        __syncthreads();                 // buf visible to all; prev compute done
        if (jt + 1 < ntiles) { issue_kv(jt + 1, buf ^ 1); CP_COMMIT(); }

        if (jt * 64 > wrow0 + 15) continue;   // tile fully masked for this warp

        const float* Kb = Ks + buf * 64 * FP;
        const float* Vb = Vs + buf * 64 * FP;

        // ---- S = Q K^T (per warp: 16 x 64)
        float s[8][4];
#pragma unroll
        for (int f = 0; f < 8; f++)
#pragma unroll
            for (int c = 0; c < 4; c++) s[f][c] = 0.f;
#pragma unroll
        for (int kk = 0; kk < 8; kk++) {
#pragma unroll
            for (int f = 0; f < 8; f++) {
                uint32_t b0 = f2tf(Kb[(f * 8 + qid) * FP + kk * 8 + qt]);
                uint32_t b1 = f2tf(Kb[(f * 8 + qid) * FP + kk * 8 + qt + 4]);
                mma_tf32(s[f], qa[kk][0], qa[kk][1], qa[kk][2], qa[kk][3], b0, b1);
            }
        }

        // ---- causal mask (only when tile reaches past warp's smallest row)
        if (jt * 64 + 63 > wrow0) {
#pragma unroll
            for (int f = 0; f < 8; f++) {
                int lc = jt * 64 + f * 8 + 2 * qt;
                if (lc > gq0)     s[f][0] = -1e30f;
                if (lc + 1 > gq0) s[f][1] = -1e30f;
                if (lc > gq1)     s[f][2] = -1e30f;
                if (lc + 1 > gq1) s[f][3] = -1e30f;
            }
        }

        // ---- online softmax (rows are quad-shared)
        float rm0 = -1e30f, rm1 = -1e30f;
#pragma unroll
        for (int f = 0; f < 8; f++) {
            rm0 = fmaxf(rm0, fmaxf(s[f][0], s[f][1]));
            rm1 = fmaxf(rm1, fmaxf(s[f][2], s[f][3]));
        }
        rm0 = fmaxf(rm0, __shfl_xor_sync(0xffffffffu, rm0, 1));
        rm0 = fmaxf(rm0, __shfl_xor_sync(0xffffffffu, rm0, 2));
        rm1 = fmaxf(rm1, __shfl_xor_sync(0xffffffffu, rm1, 1));
        rm1 = fmaxf(rm1, __shfl_xor_sync(0xffffffffu, rm1, 2));

        float mn0 = fmaxf(m0r, rm0), mn1 = fmaxf(m1r, rm1);
        float al0 = __expf(m0r - mn0), al1 = __expf(m1r - mn1);
        float rs0 = 0.f, rs1 = 0.f;
#pragma unroll
        for (int f = 0; f < 8; f++) {
            s[f][0] = __expf(s[f][0] - mn0);
            s[f][1] = __expf(s[f][1] - mn0);
            s[f][2] = __expf(s[f][2] - mn1);
            s[f][3] = __expf(s[f][3] - mn1);
            rs0 += s[f][0] + s[f][1];
            rs1 += s[f][2] + s[f][3];
        }
        rs0 += __shfl_xor_sync(0xffffffffu, rs0, 1);
        rs0 += __shfl_xor_sync(0xffffffffu, rs0, 2);
        rs1 += __shfl_xor_sync(0xffffffffu, rs1, 1);
        rs1 += __shfl_xor_sync(0xffffffffu, rs1, 2);
        l0 = l0 * al0 + rs0;
        l1 = l1 * al1 + rs1;
        m0r = mn0; m1r = mn1;
#pragma unroll
        for (int f = 0; f < 8; f++) {
            o[f][0] *= al0; o[f][1] *= al0;
            o[f][2] *= al1; o[f][3] *= al1;
        }

        // ---- stage P (tf32 bits) in per-warp smem, then PV mma into O
        __syncwarp();
#pragma unroll
        for (int f = 0; f < 8; f++) {
            float2 p0 = make_float2(__uint_as_float(f2tf(s[f][0])), __uint_as_float(f2tf(s[f][1])));
            float2 p1 = make_float2(__uint_as_float(f2tf(s[f][2])), __uint_as_float(f2tf(s[f][3])));
            *(float2*)(Pw + qid * 68 + f * 8 + 2 * qt) = p0;
            *(float2*)(Pw + (qid + 8) * 68 + f * 8 + 2 * qt) = p1;
        }
        __syncwarp();
#pragma unroll
        for (int kk = 0; kk < 8; kk++) {
            uint32_t pa0 = __float_as_uint(Pw[qid * 68 + kk * 8 + qt]);
            uint32_t pa1 = __float_as_uint(Pw[(qid + 8) * 68 + kk * 8 + qt]);
            uint32_t pa2 = __float_as_uint(Pw[qid * 68 + kk * 8 + qt + 4]);
            uint32_t pa3 = __float_as_uint(Pw[(qid + 8) * 68 + kk * 8 + qt + 4]);
#pragma unroll
            for (int f = 0; f < 8; f++) {
                uint32_t b0 = f2tf(Vb[(kk * 8 + qt) * FP + f * 8 + qid]);
                uint32_t b1 = f2tf(Vb[(kk * 8 + qt + 4) * FP + f * 8 + qid]);
                mma_tf32(o[f], pa0, pa1, pa2, pa3, b0, b1);
            }
        }
    }

    // ---- epilogue: normalize, write [B,S,H*hd]
    float inv0 = 1.f / l0, inv1 = 1.f / l1;
    size_t ro = (size_t)(b * SEQ + gq0) * D_EMBED + h * HDIM;
#pragma unroll
    for (int f = 0; f < 8; f++) {
        *(float2*)(out + ro + f * 8 + 2 * qt) =
            make_float2(o[f][0] * inv0, o[f][1] * inv0);
        *(float2*)(out + ro + 8 * D_EMBED + f * 8 + 2 * qt) =
            make_float2(o[f][2] * inv1, o[f][3] * inv1);
    }
}

// ---------------- launcher ----------------
extern "C" void kernel_launch(void* const* d_in, const int* in_sizes, int n_in,
                              void* d_out, int out_size) {
    const float* x     = (const float*)d_in[0];
    const float* Wqkv  = (const float*)d_in[1];
    const float* Aqkv  = (const float*)d_in[2];
    const float* Bqkv  = (const float*)d_in[3];
    const float* Wproj = (const float*)d_in[4];
    const float* bproj = (const float*)d_in[5];
    const float* Aproj = (const float*)d_in[6];
    const float* Bproj = (const float*)d_in[7];

    float *qkv, *attn, *xa;
    cudaGetSymbolAddress((void**)&qkv,  g_qkv);
    cudaGetSymbolAddress((void**)&attn, g_attn);
    cudaGetSymbolAddress((void**)&xa,   g_xa);

    int gsmem = 4 * 128 * GP * (int)sizeof(float);          // 73.7 KB
    cudaFuncSetAttribute(gemm_tf32_lora,
                         cudaFuncAttributeMaxDynamicSharedMemorySize, gsmem);
    int fsmem = (4 * 64 * FP + 8 * 16 * 68) * (int)sizeof(float);  // 108.5 KB
    cudaFuncSetAttribute(flash_tf32,
                         cudaFuncAttributeMaxDynamicSharedMemorySize, fsmem);

    // 1) LoRA-A for qkv
    lora_a_kernel<<<NTOK / 8, 256>>>(x, Aqkv, xa);
    // 2) QKV GEMM + LoRA-B (tf32 tensor cores, cp.async)
    gemm_tf32_lora<<<dim3(3 * D_EMBED / 128, NTOK / 128), 256, gsmem>>>(
        x, Wqkv, xa, Bqkv, nullptr, qkv, NTOK, 3 * D_EMBED, D_EMBED, 0);
    // 3) RoPE on q,k
    rope_kernel<<<(BATCH * SEQ * NHEAD * 32) / 256, 256>>>(qkv);
    // 4) causal flash attention (tf32, cp.async, 2 CTAs/SM), Br=128
    flash_tf32<<<dim3(SEQ / 128, BATCH * NHEAD), 256, fsmem>>>(qkv, attn);
    // 5) LoRA-A for proj
    lora_a_kernel<<<NTOK / 8, 256>>>(attn, Aproj, xa);
    // 6) output projection + bias + LoRA-B -> d_out
    gemm_tf32_lora<<<dim3(D_EMBED / 128, NTOK / 128), 256, gsmem>>>(
        attn, Wproj, xa, Bproj, bproj, (float*)d_out, NTOK, D_EMBED, D_EMBED, 1);
}